// round 1
// baseline (speedup 1.0000x reference)
#include <cuda_runtime.h>
#include <math.h>

#define D_MODEL 1024
#define NHEAD   16
#define DH      64
#define NLAYER  6
#define DIM_FF  4096
#define BATCH   8
#define SEQ     1024
#define M_ROWS  (BATCH*SEQ)   // 8192

// ---------------- scratch (static device globals: allocation-free) ----------
__device__ float g_x   [M_ROWS * D_MODEL];      // 32 MB residual stream
__device__ float g_qkv [M_ROWS * 3 * D_MODEL];  // 96 MB
__device__ float g_attn[M_ROWS * D_MODEL];      // 32 MB
__device__ float g_tmp [M_ROWS * D_MODEL];      // 32 MB
__device__ float g_ff  [M_ROWS * DIM_FF];       // 128 MB
__device__ float g_cls [BATCH * D_MODEL];
__device__ unsigned char g_kpm[M_ROWS];

// ---------------- mask: pad token (id==0), position 0 never masked ----------
__global__ void mask_kernel(const int* __restrict__ ids) {
    int i = blockIdx.x * blockDim.x + threadIdx.x;
    if (i < M_ROWS)
        g_kpm[i] = (ids[i] == 0 && (i & (SEQ - 1)) != 0) ? 1 : 0;
}

// ---------------- embedding: x = tok_emb[ids] + pos_emb ---------------------
__global__ void embed_kernel(const int* __restrict__ ids,
                             const float* __restrict__ tok,
                             const float* __restrict__ pos) {
    int idx4 = blockIdx.x * blockDim.x + threadIdx.x;  // over M_ROWS*D_MODEL/4
    int base = idx4 << 2;
    int bl   = base >> 10;           // row (b*L + l)
    int d    = base & 1023;
    int t    = ids[bl];
    float4 tv = *(const float4*)(tok + (size_t)t * D_MODEL + d);
    float4 pv = *(const float4*)(pos + (size_t)(bl & (SEQ - 1)) * D_MODEL + d);
    float4 o;
    o.x = tv.x + pv.x; o.y = tv.y + pv.y; o.z = tv.z + pv.z; o.w = tv.w + pv.w;
    *(float4*)(g_x + (size_t)base) = o;
}

// ---------------- SGEMM (NT): C[M,N] = A[M,K] @ B[N,K]^T + bias, opt GELU ----
template <int GELU>
__global__ void __launch_bounds__(256)
sgemm_nt(const float* __restrict__ A, const float* __restrict__ Bm,
         const float* __restrict__ bias, float* __restrict__ C,
         int M, int N, int K) {
    constexpr int BK = 16;
    __shared__ float As[BK][128];
    __shared__ float Bs[BK][128];

    int tid = threadIdx.x;
    int m0 = blockIdx.y << 7;
    int n0 = blockIdx.x << 7;

    int lr = tid >> 2;           // 0..63
    int lc = (tid & 3) << 2;     // 0,4,8,12
    const float* Ap = A  + (size_t)(m0 + lr) * K + lc;
    const float* Bp = Bm + (size_t)(n0 + lr) * K + lc;

    int ty = tid >> 4;           // rows ty*8..
    int tx = tid & 15;           // cols tx*8..

    float acc[8][8];
#pragma unroll
    for (int i = 0; i < 8; i++)
#pragma unroll
        for (int j = 0; j < 8; j++) acc[i][j] = 0.f;

    for (int k0 = 0; k0 < K; k0 += BK) {
        float4 a0 = *(const float4*)(Ap + k0);
        float4 a1 = *(const float4*)(Ap + (size_t)64 * K + k0);
        float4 b0 = *(const float4*)(Bp + k0);
        float4 b1 = *(const float4*)(Bp + (size_t)64 * K + k0);
        __syncthreads();
        As[lc + 0][lr]      = a0.x; As[lc + 1][lr]      = a0.y;
        As[lc + 2][lr]      = a0.z; As[lc + 3][lr]      = a0.w;
        As[lc + 0][lr + 64] = a1.x; As[lc + 1][lr + 64] = a1.y;
        As[lc + 2][lr + 64] = a1.z; As[lc + 3][lr + 64] = a1.w;
        Bs[lc + 0][lr]      = b0.x; Bs[lc + 1][lr]      = b0.y;
        Bs[lc + 2][lr]      = b0.z; Bs[lc + 3][lr]      = b0.w;
        Bs[lc + 0][lr + 64] = b1.x; Bs[lc + 1][lr + 64] = b1.y;
        Bs[lc + 2][lr + 64] = b1.z; Bs[lc + 3][lr + 64] = b1.w;
        __syncthreads();
#pragma unroll
        for (int k = 0; k < BK; k++) {
            float ar[8], br[8];
            *(float4*)(ar)     = *(const float4*)&As[k][ty * 8];
            *(float4*)(ar + 4) = *(const float4*)&As[k][ty * 8 + 4];
            *(float4*)(br)     = *(const float4*)&Bs[k][tx * 8];
            *(float4*)(br + 4) = *(const float4*)&Bs[k][tx * 8 + 4];
#pragma unroll
            for (int i = 0; i < 8; i++)
#pragma unroll
                for (int j = 0; j < 8; j++)
                    acc[i][j] = fmaf(ar[i], br[j], acc[i][j]);
        }
    }

#pragma unroll
    for (int i = 0; i < 8; i++) {
        int m = m0 + ty * 8 + i;
#pragma unroll
        for (int j0 = 0; j0 < 8; j0 += 4) {
            float4 o;
            float* po = &o.x;
#pragma unroll
            for (int j = 0; j < 4; j++) {
                int n = n0 + tx * 8 + j0 + j;
                float v = acc[i][j0 + j] + bias[n];
                if (GELU) v = 0.5f * v * (1.0f + erff(v * 0.70710678118654752f));
                po[j] = v;
            }
            *(float4*)(C + (size_t)m * N + n0 + tx * 8 + j0) = o;
        }
    }
}

// ---------------- fused attention (online softmax, 64-query tiles) ----------
#define ATTN_PAD 68
#define ATTN_SMEM ((4 * 64 * ATTN_PAD + 4 * 64) * 4)

__global__ void __launch_bounds__(256)
attn_kernel(float* __restrict__ out, const float* __restrict__ qkv) {
    extern __shared__ float sm[];
    float* Qs   = sm;
    float* Ks   = Qs + 64 * ATTN_PAD;
    float* Vs   = Ks + 64 * ATTN_PAD;
    float* Ss   = Vs + 64 * ATTN_PAD;
    float* mrow = Ss + 64 * ATTN_PAD;
    float* lrow = mrow + 64;
    float* arow = lrow + 64;
    float* msk  = arow + 64;

    int tid = threadIdx.x;
    int q0  = blockIdx.x << 6;
    int h   = blockIdx.y;
    int b   = blockIdx.z;
    int ty  = tid >> 4;
    int tx  = tid & 15;

#pragma unroll
    for (int rep = 0; rep < 4; rep++) {
        int idx = rep * 256 + tid;
        int r = idx >> 4, c = (idx & 15) << 2;
        *(float4*)&Qs[r * ATTN_PAD + c] =
            *(const float4*)(qkv + (size_t)(b * SEQ + q0 + r) * 3072 + h * DH + c);
    }
    if (tid < 64) { mrow[tid] = -1e30f; lrow[tid] = 0.f; }

    float o[4][4];
#pragma unroll
    for (int i = 0; i < 4; i++)
#pragma unroll
        for (int j = 0; j < 4; j++) o[i][j] = 0.f;

    for (int kt = 0; kt < 16; kt++) {
        int k0 = kt << 6;
#pragma unroll
        for (int rep = 0; rep < 4; rep++) {
            int idx = rep * 256 + tid;
            int r = idx >> 4, c = (idx & 15) << 2;
            size_t rb = (size_t)(b * SEQ + k0 + r) * 3072 + h * DH + c;
            *(float4*)&Ks[r * ATTN_PAD + c] = *(const float4*)(qkv + rb + D_MODEL);
            *(float4*)&Vs[r * ATTN_PAD + c] = *(const float4*)(qkv + rb + 2 * D_MODEL);
        }
        if (tid < 64) msk[tid] = g_kpm[b * SEQ + k0 + tid] ? -1e9f : 0.f;
        __syncthreads();

        float s[4][4];
#pragma unroll
        for (int i = 0; i < 4; i++)
#pragma unroll
            for (int j = 0; j < 4; j++) s[i][j] = 0.f;

        const float4* Q4 = (const float4*)Qs;
        const float4* K4 = (const float4*)Ks;
#pragma unroll
        for (int d = 0; d < 16; d++) {
            float4 qa[4], kb[4];
#pragma unroll
            for (int i = 0; i < 4; i++) qa[i] = Q4[(ty * 4 + i) * (ATTN_PAD / 4) + d];
#pragma unroll
            for (int j = 0; j < 4; j++) kb[j] = K4[(tx * 4 + j) * (ATTN_PAD / 4) + d];
#pragma unroll
            for (int i = 0; i < 4; i++)
#pragma unroll
                for (int j = 0; j < 4; j++)
                    s[i][j] += qa[i].x * kb[j].x + qa[i].y * kb[j].y +
                               qa[i].z * kb[j].z + qa[i].w * kb[j].w;
        }
#pragma unroll
        for (int i = 0; i < 4; i++)
#pragma unroll
            for (int j = 0; j < 4; j++)
                Ss[(ty * 4 + i) * ATTN_PAD + tx * 4 + j] = s[i][j] * 0.125f + msk[tx * 4 + j];
        __syncthreads();

        if (tid < 64) {
            int r = tid;
            float mo = mrow[r], mx = mo;
#pragma unroll 8
            for (int k = 0; k < 64; k++) mx = fmaxf(mx, Ss[r * ATTN_PAD + k]);
            float al = expf(mo - mx);
            float sum = 0.f;
#pragma unroll 8
            for (int k = 0; k < 64; k++) {
                float p = expf(Ss[r * ATTN_PAD + k] - mx);
                Ss[r * ATTN_PAD + k] = p;
                sum += p;
            }
            lrow[r] = lrow[r] * al + sum;
            mrow[r] = mx;
            arow[r] = al;
        }
        __syncthreads();

        const float4* V4 = (const float4*)Vs;
#pragma unroll
        for (int i = 0; i < 4; i++) {
            float al = arow[ty * 4 + i];
#pragma unroll
            for (int j = 0; j < 4; j++) o[i][j] *= al;
        }
#pragma unroll 8
        for (int p = 0; p < 64; p++) {
            float4 vb = V4[p * (ATTN_PAD / 4) + tx];
#pragma unroll
            for (int i = 0; i < 4; i++) {
                float a = Ss[(ty * 4 + i) * ATTN_PAD + p];
                o[i][0] = fmaf(a, vb.x, o[i][0]);
                o[i][1] = fmaf(a, vb.y, o[i][1]);
                o[i][2] = fmaf(a, vb.z, o[i][2]);
                o[i][3] = fmaf(a, vb.w, o[i][3]);
            }
        }
        __syncthreads();
    }

#pragma unroll
    for (int i = 0; i < 4; i++) {
        float inv = 1.0f / lrow[ty * 4 + i];
        float4 ov;
        ov.x = o[i][0] * inv; ov.y = o[i][1] * inv;
        ov.z = o[i][2] * inv; ov.w = o[i][3] * inv;
        *(float4*)(out + (size_t)(b * SEQ + q0 + ty * 4 + i) * D_MODEL + h * DH + tx * 4) = ov;
    }
}

// ---------------- LayerNorm (+optional residual add), 1 block = 1 row -------
template <bool HASD>
__global__ void ln_kernel(float* __restrict__ out, const float* __restrict__ x,
                          const float* __restrict__ delta,
                          const float* __restrict__ g, const float* __restrict__ bta,
                          size_t in_row_stride) {
    __shared__ float vals[D_MODEL];
    __shared__ float red[256];
    __shared__ float red2[256];
    int row = blockIdx.x, tid = threadIdx.x;
    const float* xr = x + (size_t)row * in_row_stride;

    float4 v = *(const float4*)(xr + tid * 4);
    if (HASD) {
        float4 dv = *(const float4*)(delta + (size_t)row * D_MODEL + tid * 4);
        v.x += dv.x; v.y += dv.y; v.z += dv.z; v.w += dv.w;
    }
    *(float4*)&vals[tid * 4] = v;
    red[tid]  = v.x + v.y + v.z + v.w;
    red2[tid] = v.x * v.x + v.y * v.y + v.z * v.z + v.w * v.w;
    __syncthreads();
#pragma unroll
    for (int off = 128; off > 0; off >>= 1) {
        if (tid < off) { red[tid] += red[tid + off]; red2[tid] += red2[tid + off]; }
        __syncthreads();
    }
    float mean = red[0] * (1.0f / D_MODEL);
    float var  = red2[0] * (1.0f / D_MODEL) - mean * mean;
    float inv  = rsqrtf(var + 1e-5f);

    float4 vv = *(float4*)&vals[tid * 4];
    float4 g4 = *(const float4*)(g + tid * 4);
    float4 b4 = *(const float4*)(bta + tid * 4);
    float4 ov;
    ov.x = (vv.x - mean) * inv * g4.x + b4.x;
    ov.y = (vv.y - mean) * inv * g4.y + b4.y;
    ov.z = (vv.z - mean) * inv * g4.z + b4.z;
    ov.w = (vv.w - mean) * inv * g4.w + b4.w;
    *(float4*)(out + (size_t)row * D_MODEL + tid * 4) = ov;
}

// ---------------- head: out[b,n] = dot(cls_ln[b], W[n]) + hb[n] -------------
__global__ void head_kernel(float* __restrict__ out, const float* __restrict__ W,
                            const float* __restrict__ hb) {
    __shared__ float c[D_MODEL];
    int b = blockIdx.y;
    int n = blockIdx.x * 128 + threadIdx.x;
#pragma unroll
    for (int rep = 0; rep < 2; rep++) {
        int idx = rep * 128 + threadIdx.x;
        *(float4*)&c[idx * 4] = *(const float4*)(g_cls + (size_t)b * D_MODEL + idx * 4);
    }
    __syncthreads();
    const float4* W4 = (const float4*)(W + (size_t)n * D_MODEL);
    const float4* c4 = (const float4*)c;
    float acc = 0.f;
#pragma unroll 8
    for (int k = 0; k < D_MODEL / 4; k++) {
        float4 w = W4[k], cc = c4[k];
        acc += w.x * cc.x + w.y * cc.y + w.z * cc.z + w.w * cc.w;
    }
    out[(size_t)b * D_MODEL + n] = acc + hb[n];
}

// ---------------- launcher ---------------------------------------------------
extern "C" void kernel_launch(void* const* d_in, const int* in_sizes, int n_in,
                              void* d_out, int out_size) {
    const int*   ids  = (const int*)  d_in[0];
    const float* tok  = (const float*)d_in[1];
    const float* pos  = (const float*)d_in[2];
    const float* Wqkv = (const float*)d_in[3];
    const float* bqkv = (const float*)d_in[4];
    const float* Wo   = (const float*)d_in[5];
    const float* bo   = (const float*)d_in[6];
    const float* ln1g = (const float*)d_in[7];
    const float* ln1b = (const float*)d_in[8];
    const float* W1   = (const float*)d_in[9];
    const float* b1   = (const float*)d_in[10];
    const float* W2   = (const float*)d_in[11];
    const float* b2   = (const float*)d_in[12];
    const float* ln2g = (const float*)d_in[13];
    const float* ln2b = (const float*)d_in[14];
    const float* hg   = (const float*)d_in[15];
    const float* hbln = (const float*)d_in[16];
    const float* hW   = (const float*)d_in[17];
    const float* hb   = (const float*)d_in[18];
    float* out = (float*)d_out;

    float *px, *pqkv, *pattn, *ptmp, *pff, *pcls;
    cudaGetSymbolAddress((void**)&px,    g_x);
    cudaGetSymbolAddress((void**)&pqkv,  g_qkv);
    cudaGetSymbolAddress((void**)&pattn, g_attn);
    cudaGetSymbolAddress((void**)&ptmp,  g_tmp);
    cudaGetSymbolAddress((void**)&pff,   g_ff);
    cudaGetSymbolAddress((void**)&pcls,  g_cls);

    cudaFuncSetAttribute(attn_kernel, cudaFuncAttributeMaxDynamicSharedMemorySize,
                         ATTN_SMEM);

    mask_kernel <<<M_ROWS / 256, 256>>>(ids);
    embed_kernel<<<M_ROWS * D_MODEL / 1024, 256>>>(ids, tok, pos);

    for (int i = 0; i < NLAYER; i++) {
        const float* Wqkv_i = Wqkv + (size_t)i * 3 * D_MODEL * D_MODEL;
        const float* Wo_i   = Wo   + (size_t)i * D_MODEL * D_MODEL;
        const float* W1_i   = W1   + (size_t)i * DIM_FF * D_MODEL;
        const float* W2_i   = W2   + (size_t)i * D_MODEL * DIM_FF;

        sgemm_nt<0><<<dim3(3 * D_MODEL / 128, M_ROWS / 128), 256>>>(
            px, Wqkv_i, bqkv + i * 3 * D_MODEL, pqkv, M_ROWS, 3 * D_MODEL, D_MODEL);

        attn_kernel<<<dim3(SEQ / 64, NHEAD, BATCH), 256, ATTN_SMEM>>>(pattn, pqkv);

        sgemm_nt<0><<<dim3(D_MODEL / 128, M_ROWS / 128), 256>>>(
            pattn, Wo_i, bo + i * D_MODEL, ptmp, M_ROWS, D_MODEL, D_MODEL);

        ln_kernel<true><<<M_ROWS, 256>>>(px, px, ptmp,
                                         ln1g + i * D_MODEL, ln1b + i * D_MODEL, D_MODEL);

        sgemm_nt<1><<<dim3(DIM_FF / 128, M_ROWS / 128), 256>>>(
            px, W1_i, b1 + i * DIM_FF, pff, M_ROWS, DIM_FF, D_MODEL);

        sgemm_nt<0><<<dim3(D_MODEL / 128, M_ROWS / 128), 256>>>(
            pff, W2_i, b2 + i * D_MODEL, ptmp, M_ROWS, D_MODEL, DIM_FF);

        ln_kernel<true><<<M_ROWS, 256>>>(px, px, ptmp,
                                         ln2g + i * D_MODEL, ln2b + i * D_MODEL, D_MODEL);
    }

    ln_kernel<false><<<BATCH, 256>>>(pcls, px, nullptr, hg, hbln,
                                     (size_t)SEQ * D_MODEL);
    head_kernel<<<dim3(D_MODEL / 128, BATCH), 128>>>(out, hW, hb);
}

// round 3
// speedup vs baseline: 1.6756x; 1.6756x over previous
#include <cuda_runtime.h>
#include <cuda_bf16.h>
#include <math.h>
#include <stdint.h>

#define D_MODEL 1024
#define NHEAD   16
#define DH      64
#define NLAYER  6
#define DIM_FF  4096
#define BATCH   8
#define SEQ     1024
#define M_ROWS  (BATCH*SEQ)   // 8192

// ---------------- scratch (static device globals: allocation-free) ----------
__device__ float g_x   [M_ROWS * D_MODEL];      // residual stream (fp32)
__device__ float g_qkv [M_ROWS * 3 * D_MODEL];  // qkv fp32 (attention input)
__device__ float g_tmp [M_ROWS * D_MODEL];      // GEMM fp32 outputs (Wo / FF2)
__device__ float g_cls [BATCH * D_MODEL];
__device__ unsigned char g_kpm[M_ROWS];

// bf16 hi/lo operand arrays
__device__ __nv_bfloat16 g_wh[75497472];        // all weights hi (12582912/layer)
__device__ __nv_bfloat16 g_wl[75497472];        // all weights lo
__device__ __nv_bfloat16 g_xh[M_ROWS * D_MODEL];
__device__ __nv_bfloat16 g_xl[M_ROWS * D_MODEL];
__device__ __nv_bfloat16 g_ah[M_ROWS * D_MODEL];
__device__ __nv_bfloat16 g_al[M_ROWS * D_MODEL];
__device__ __nv_bfloat16 g_fh[M_ROWS * DIM_FF];
__device__ __nv_bfloat16 g_fl[M_ROWS * DIM_FF];

// ---------------- helpers ----------------------------------------------------
__device__ __forceinline__ uint32_t smem_u32(const void* p) {
    uint32_t a;
    asm("{ .reg .u64 t; cvta.to.shared.u64 t, %1; cvt.u32.u64 %0, t; }"
        : "=r"(a) : "l"(p));
    return a;
}

__device__ __forceinline__ uint32_t lds32(uint32_t addr) {
    uint32_t v;
    asm volatile("ld.shared.b32 %0, [%1];" : "=r"(v) : "r"(addr));
    return v;
}

#define CPA16(dst, src) \
    asm volatile("cp.async.cg.shared.global [%0], [%1], 16;" \
                 :: "r"(dst), "l"(src) : "memory")
#define CPA_COMMIT() asm volatile("cp.async.commit_group;" ::: "memory")
#define CPA_WAIT1()  asm volatile("cp.async.wait_group 1;" ::: "memory")
#define CPA_WAIT0()  asm volatile("cp.async.wait_group 0;" ::: "memory")

// bf16 mma m16n8k16, fp32 accumulate (HMMA, baseline PTX sm_80+)
__device__ __forceinline__ void mma16816(float* d, const uint32_t* a, const uint32_t* b) {
    asm volatile(
        "mma.sync.aligned.m16n8k16.row.col.f32.bf16.bf16.f32 "
        "{%0,%1,%2,%3}, {%4,%5,%6,%7}, {%8,%9}, {%0,%1,%2,%3};"
        : "+f"(d[0]), "+f"(d[1]), "+f"(d[2]), "+f"(d[3])
        : "r"(a[0]), "r"(a[1]), "r"(a[2]), "r"(a[3]), "r"(b[0]), "r"(b[1]));
}

__device__ __forceinline__ void split_store(__nv_bfloat16* __restrict__ h,
                                            __nv_bfloat16* __restrict__ l,
                                            size_t off, float v) {
    __nv_bfloat16 hv = __float2bfloat16(v);
    h[off] = hv;
    l[off] = __float2bfloat16(v - __bfloat162float(hv));
}

// ---------------- mask -------------------------------------------------------
__global__ void mask_kernel(const int* __restrict__ ids) {
    int i = blockIdx.x * blockDim.x + threadIdx.x;
    if (i < M_ROWS)
        g_kpm[i] = (ids[i] == 0 && (i & (SEQ - 1)) != 0) ? 1 : 0;
}

// ---------------- embedding: x = tok_emb[ids] + pos_emb (+ bf16 hi/lo) ------
__global__ void embed_kernel(const int* __restrict__ ids,
                             const float* __restrict__ tok,
                             const float* __restrict__ pos) {
    int idx4 = blockIdx.x * blockDim.x + threadIdx.x;
    int base = idx4 << 2;
    int bl   = base >> 10;
    int d    = base & 1023;
    int t    = ids[bl];
    float4 tv = *(const float4*)(tok + (size_t)t * D_MODEL + d);
    float4 pv = *(const float4*)(pos + (size_t)(bl & (SEQ - 1)) * D_MODEL + d);
    float4 o;
    o.x = tv.x + pv.x; o.y = tv.y + pv.y; o.z = tv.z + pv.z; o.w = tv.w + pv.w;
    *(float4*)(g_x + (size_t)base) = o;
    split_store(g_xh, g_xl, base + 0, o.x);
    split_store(g_xh, g_xl, base + 1, o.y);
    split_store(g_xh, g_xl, base + 2, o.z);
    split_store(g_xh, g_xl, base + 3, o.w);
}

// ---------------- weight fp32 -> bf16 hi/lo ---------------------------------
__global__ void cvt_kernel(const float* __restrict__ s,
                           __nv_bfloat16* __restrict__ h,
                           __nv_bfloat16* __restrict__ l, int n4) {
    int i = blockIdx.x * blockDim.x + threadIdx.x;
    if (i >= n4) return;
    float4 v = ((const float4*)s)[i];
    size_t b = (size_t)i << 2;
    split_store(h, l, b + 0, v.x);
    split_store(h, l, b + 1, v.y);
    split_store(h, l, b + 2, v.z);
    split_store(h, l, b + 3, v.w);
}

// ---------------- mma.sync GEMM: C = A @ B^T + bias --------------------------
// A: [M,K] bf16 hi/lo, B: [N,K] bf16 hi/lo, 3-pass split, fp32 accum in regs.
// CTA tile 128x128, BK=32, 2-stage cp.async pipeline, 256 threads (2x4 warps),
// warp tile 64x32 (4 m16-tiles x 4 n8-tiles).
// MODE 0: fp32 out. MODE 1: exact GELU -> bf16 hi/lo out.
#define ROWB   80                 // padded row bytes (64B data + 16B pad)
#define TILEB  (128 * ROWB)       // 10240 per operand tile
#define STG    (4 * TILEB)        // 40960 per stage
#define GSMEM2 (2 * STG)          // 81920

template <int MODE>
__global__ void __launch_bounds__(256, 1)
gemm_mma(const __nv_bfloat16* __restrict__ Ah, const __nv_bfloat16* __restrict__ Al,
         const __nv_bfloat16* __restrict__ Bh, const __nv_bfloat16* __restrict__ Bl,
         const float* __restrict__ bias,
         float* __restrict__ Cf,
         __nv_bfloat16* __restrict__ Ch, __nv_bfloat16* __restrict__ Cl,
         int K, int Ntot)
{
    extern __shared__ char sm8[];
    uint32_t sb = smem_u32(sm8);
    int tid = threadIdx.x, wid = tid >> 5, lane = tid & 31;
    int m0 = blockIdx.y << 7, n0 = blockIdx.x << 7;
    int wm = wid & 1, wn = wid >> 1;        // warp grid 2 (M) x 4 (N)
    int g = lane >> 2, q = lane & 3;

    // loader mapping: 256 threads, each loads 16B chunks
    int lr = tid >> 2;          // 0..63 (row within 64-row half)
    int lcch = tid & 3;         // 0..3  (16B chunk within 64B row)

    float acc[4][4][4];
#pragma unroll
    for (int mi = 0; mi < 4; ++mi)
#pragma unroll
        for (int ni = 0; ni < 4; ++ni)
#pragma unroll
            for (int r = 0; r < 4; ++r) acc[mi][ni][r] = 0.f;

    int NC = K >> 5;

    // ---- stage loader (cp.async) ----
    auto load_stage = [&](int s, int c) {
        uint32_t st = sb + s * STG;
        long kb = (long)c << 5;
#pragma unroll
        for (int p = 0; p < 2; ++p) {
            int r = p * 64 + lr;
            uint32_t so = (uint32_t)r * ROWB + lcch * 16;
            const __nv_bfloat16* a_src = Ah + (size_t)(m0 + r) * K + kb + lcch * 8;
            const __nv_bfloat16* al_src = Al + (size_t)(m0 + r) * K + kb + lcch * 8;
            const __nv_bfloat16* b_src = Bh + (size_t)(n0 + r) * K + kb + lcch * 8;
            const __nv_bfloat16* bl_src = Bl + (size_t)(n0 + r) * K + kb + lcch * 8;
            CPA16(st + so,              a_src);
            CPA16(st + TILEB + so,      al_src);
            CPA16(st + 2 * TILEB + so,  b_src);
            CPA16(st + 3 * TILEB + so,  bl_src);
        }
    };

    load_stage(0, 0);
    CPA_COMMIT();

    for (int c = 0; c < NC; ++c) {
        if (c + 1 < NC) {
            load_stage((c + 1) & 1, c + 1);
            CPA_COMMIT();
            CPA_WAIT1();
        } else {
            CPA_WAIT0();
        }
        __syncthreads();

        uint32_t base = sb + (uint32_t)(c & 1) * STG;
        uint32_t aH = base, aL = base + TILEB;
        uint32_t bH = base + 2 * TILEB, bL = base + 3 * TILEB;
        uint32_t aoff = (uint32_t)(wm * 64 + g) * ROWB + q * 4;
        uint32_t boff = (uint32_t)(wn * 32 + g) * ROWB + q * 4;

#pragma unroll
        for (int ks = 0; ks < 2; ++ks) {
            uint32_t ko = ks * 32;
            uint32_t ah[4][4], al[4][4];
#pragma unroll
            for (int mi = 0; mi < 4; ++mi) {
                uint32_t r0 = aoff + mi * (16 * ROWB) + ko;
                ah[mi][0] = lds32(aH + r0);
                ah[mi][1] = lds32(aH + r0 + 8 * ROWB);
                ah[mi][2] = lds32(aH + r0 + 16);
                ah[mi][3] = lds32(aH + r0 + 8 * ROWB + 16);
                al[mi][0] = lds32(aL + r0);
                al[mi][1] = lds32(aL + r0 + 8 * ROWB);
                al[mi][2] = lds32(aL + r0 + 16);
                al[mi][3] = lds32(aL + r0 + 8 * ROWB + 16);
            }
#pragma unroll
            for (int ni = 0; ni < 4; ++ni) {
                uint32_t r0 = boff + ni * (8 * ROWB) + ko;
                uint32_t bh[2], bl2[2];
                bh[0]  = lds32(bH + r0);
                bh[1]  = lds32(bH + r0 + 16);
                bl2[0] = lds32(bL + r0);
                bl2[1] = lds32(bL + r0 + 16);
#pragma unroll
                for (int mi = 0; mi < 4; ++mi) {
                    mma16816(acc[mi][ni], ah[mi], bh);
                    mma16816(acc[mi][ni], ah[mi], bl2);
                    mma16816(acc[mi][ni], al[mi], bh);
                }
            }
        }
        __syncthreads();
    }

    // ---- epilogue: direct float2-coalesced stores ----
#pragma unroll
    for (int mi = 0; mi < 4; ++mi) {
        int r0 = m0 + wm * 64 + mi * 16 + g;
#pragma unroll
        for (int ni = 0; ni < 4; ++ni) {
            int col = n0 + wn * 32 + ni * 8 + q * 2;
            float2 bv = *(const float2*)(bias + col);
            float* a = acc[mi][ni];
#pragma unroll
            for (int half = 0; half < 2; ++half) {
                int row = r0 + half * 8;
                float v0 = a[half * 2 + 0] + bv.x;
                float v1 = a[half * 2 + 1] + bv.y;
                size_t off = (size_t)row * Ntot + col;
                if (MODE == 0) {
                    float2 o; o.x = v0; o.y = v1;
                    *(float2*)(Cf + off) = o;
                } else {
                    v0 = 0.5f * v0 * (1.0f + erff(v0 * 0.70710678118654752f));
                    v1 = 0.5f * v1 * (1.0f + erff(v1 * 0.70710678118654752f));
                    __nv_bfloat16 h0 = __float2bfloat16(v0);
                    __nv_bfloat16 h1 = __float2bfloat16(v1);
                    __nv_bfloat162 hp, lp;
                    hp.x = h0; hp.y = h1;
                    lp.x = __float2bfloat16(v0 - __bfloat162float(h0));
                    lp.y = __float2bfloat16(v1 - __bfloat162float(h1));
                    *(__nv_bfloat162*)(Ch + off) = hp;
                    *(__nv_bfloat162*)(Cl + off) = lp;
                }
            }
        }
    }
}

// ---------------- fused attention (online softmax) — writes bf16 hi/lo ------
#define ATTN_PAD 68
#define ATTN_SMEM ((4 * 64 * ATTN_PAD + 4 * 64) * 4)

__global__ void __launch_bounds__(256)
attn_kernel(const float* __restrict__ qkv) {
    extern __shared__ float sm[];
    float* Qs   = sm;
    float* Ks   = Qs + 64 * ATTN_PAD;
    float* Vs   = Ks + 64 * ATTN_PAD;
    float* Ss   = Vs + 64 * ATTN_PAD;
    float* mrow = Ss + 64 * ATTN_PAD;
    float* lrow = mrow + 64;
    float* arow = lrow + 64;
    float* msk  = arow + 64;

    int tid = threadIdx.x;
    int q0  = blockIdx.x << 6;
    int h   = blockIdx.y;
    int b   = blockIdx.z;
    int ty  = tid >> 4;
    int tx  = tid & 15;

#pragma unroll
    for (int rep = 0; rep < 4; rep++) {
        int idx = rep * 256 + tid;
        int r = idx >> 4, c = (idx & 15) << 2;
        *(float4*)&Qs[r * ATTN_PAD + c] =
            *(const float4*)(qkv + (size_t)(b * SEQ + q0 + r) * 3072 + h * DH + c);
    }
    if (tid < 64) { mrow[tid] = -1e30f; lrow[tid] = 0.f; }

    float o[4][4];
#pragma unroll
    for (int i = 0; i < 4; i++)
#pragma unroll
        for (int j = 0; j < 4; j++) o[i][j] = 0.f;

    for (int kt = 0; kt < 16; kt++) {
        int k0 = kt << 6;
#pragma unroll
        for (int rep = 0; rep < 4; rep++) {
            int idx = rep * 256 + tid;
            int r = idx >> 4, c = (idx & 15) << 2;
            size_t rb = (size_t)(b * SEQ + k0 + r) * 3072 + h * DH + c;
            *(float4*)&Ks[r * ATTN_PAD + c] = *(const float4*)(qkv + rb + D_MODEL);
            *(float4*)&Vs[r * ATTN_PAD + c] = *(const float4*)(qkv + rb + 2 * D_MODEL);
        }
        if (tid < 64) msk[tid] = g_kpm[b * SEQ + k0 + tid] ? -1e9f : 0.f;
        __syncthreads();

        float s[4][4];
#pragma unroll
        for (int i = 0; i < 4; i++)
#pragma unroll
            for (int j = 0; j < 4; j++) s[i][j] = 0.f;

        const float4* Q4 = (const float4*)Qs;
        const float4* K4 = (const float4*)Ks;
#pragma unroll
        for (int d = 0; d < 16; d++) {
            float4 qa[4], kb[4];
#pragma unroll
            for (int i = 0; i < 4; i++) qa[i] = Q4[(ty * 4 + i) * (ATTN_PAD / 4) + d];
#pragma unroll
            for (int j = 0; j < 4; j++) kb[j] = K4[(tx * 4 + j) * (ATTN_PAD / 4) + d];
#pragma unroll
            for (int i = 0; i < 4; i++)
#pragma unroll
                for (int j = 0; j < 4; j++)
                    s[i][j] += qa[i].x * kb[j].x + qa[i].y * kb[j].y +
                               qa[i].z * kb[j].z + qa[i].w * kb[j].w;
        }
#pragma unroll
        for (int i = 0; i < 4; i++)
#pragma unroll
            for (int j = 0; j < 4; j++)
                Ss[(ty * 4 + i) * ATTN_PAD + tx * 4 + j] = s[i][j] * 0.125f + msk[tx * 4 + j];
        __syncthreads();

        if (tid < 64) {
            int r = tid;
            float mo = mrow[r], mx = mo;
#pragma unroll 8
            for (int k = 0; k < 64; k++) mx = fmaxf(mx, Ss[r * ATTN_PAD + k]);
            float al = expf(mo - mx);
            float sum = 0.f;
#pragma unroll 8
            for (int k = 0; k < 64; k++) {
                float p = expf(Ss[r * ATTN_PAD + k] - mx);
                Ss[r * ATTN_PAD + k] = p;
                sum += p;
            }
            lrow[r] = lrow[r] * al + sum;
            mrow[r] = mx;
            arow[r] = al;
        }
        __syncthreads();

        const float4* V4 = (const float4*)Vs;
#pragma unroll
        for (int i = 0; i < 4; i++) {
            float al = arow[ty * 4 + i];
#pragma unroll
            for (int j = 0; j < 4; j++) o[i][j] *= al;
        }
#pragma unroll 8
        for (int p = 0; p < 64; p++) {
            float4 vb = V4[p * (ATTN_PAD / 4) + tx];
#pragma unroll
            for (int i = 0; i < 4; i++) {
                float a = Ss[(ty * 4 + i) * ATTN_PAD + p];
                o[i][0] = fmaf(a, vb.x, o[i][0]);
                o[i][1] = fmaf(a, vb.y, o[i][1]);
                o[i][2] = fmaf(a, vb.z, o[i][2]);
                o[i][3] = fmaf(a, vb.w, o[i][3]);
            }
        }
        __syncthreads();
    }

#pragma unroll
    for (int i = 0; i < 4; i++) {
        float inv = 1.0f / lrow[ty * 4 + i];
        size_t off = (size_t)(b * SEQ + q0 + ty * 4 + i) * D_MODEL + h * DH + tx * 4;
        split_store(g_ah, g_al, off + 0, o[i][0] * inv);
        split_store(g_ah, g_al, off + 1, o[i][1] * inv);
        split_store(g_ah, g_al, off + 2, o[i][2] * inv);
        split_store(g_ah, g_al, off + 3, o[i][3] * inv);
    }
}

// ---------------- LayerNorm (+residual) (+bf16 hi/lo out) -------------------
template <bool HASD, bool WB>
__global__ void ln_kernel(float* __restrict__ out,
                          __nv_bfloat16* __restrict__ oh, __nv_bfloat16* __restrict__ ol,
                          const float* __restrict__ x, const float* __restrict__ delta,
                          const float* __restrict__ g, const float* __restrict__ bta,
                          size_t in_row_stride) {
    __shared__ float vals[D_MODEL];
    __shared__ float red[256];
    __shared__ float red2[256];
    int row = blockIdx.x, tid = threadIdx.x;
    const float* xr = x + (size_t)row * in_row_stride;

    float4 v = *(const float4*)(xr + tid * 4);
    if (HASD) {
        float4 dv = *(const float4*)(delta + (size_t)row * D_MODEL + tid * 4);
        v.x += dv.x; v.y += dv.y; v.z += dv.z; v.w += dv.w;
    }
    *(float4*)&vals[tid * 4] = v;
    red[tid]  = v.x + v.y + v.z + v.w;
    red2[tid] = v.x * v.x + v.y * v.y + v.z * v.z + v.w * v.w;
    __syncthreads();
#pragma unroll
    for (int off = 128; off > 0; off >>= 1) {
        if (tid < off) { red[tid] += red[tid + off]; red2[tid] += red2[tid + off]; }
        __syncthreads();
    }
    float mean = red[0] * (1.0f / D_MODEL);
    float var  = red2[0] * (1.0f / D_MODEL) - mean * mean;
    float inv  = rsqrtf(var + 1e-5f);

    float4 vv = *(float4*)&vals[tid * 4];
    float4 g4 = *(const float4*)(g + tid * 4);
    float4 b4 = *(const float4*)(bta + tid * 4);
    float4 ov;
    ov.x = (vv.x - mean) * inv * g4.x + b4.x;
    ov.y = (vv.y - mean) * inv * g4.y + b4.y;
    ov.z = (vv.z - mean) * inv * g4.z + b4.z;
    ov.w = (vv.w - mean) * inv * g4.w + b4.w;
    size_t base = (size_t)row * D_MODEL + tid * 4;
    *(float4*)(out + base) = ov;
    if (WB) {
        split_store(oh, ol, base + 0, ov.x);
        split_store(oh, ol, base + 1, ov.y);
        split_store(oh, ol, base + 2, ov.z);
        split_store(oh, ol, base + 3, ov.w);
    }
}

// ---------------- head -------------------------------------------------------
__global__ void head_kernel(float* __restrict__ out, const float* __restrict__ W,
                            const float* __restrict__ hb) {
    __shared__ float c[D_MODEL];
    int b = blockIdx.y;
    int n = blockIdx.x * 128 + threadIdx.x;
#pragma unroll
    for (int rep = 0; rep < 2; rep++) {
        int idx = rep * 128 + threadIdx.x;
        *(float4*)&c[idx * 4] = *(const float4*)(g_cls + (size_t)b * D_MODEL + idx * 4);
    }
    __syncthreads();
    const float4* W4 = (const float4*)(W + (size_t)n * D_MODEL);
    const float4* c4 = (const float4*)c;
    float acc = 0.f;
#pragma unroll 8
    for (int k = 0; k < D_MODEL / 4; k++) {
        float4 w = W4[k], cc = c4[k];
        acc += w.x * cc.x + w.y * cc.y + w.z * cc.z + w.w * cc.w;
    }
    out[(size_t)b * D_MODEL + n] = acc + hb[n];
}

// ---------------- launcher ---------------------------------------------------
extern "C" void kernel_launch(void* const* d_in, const int* in_sizes, int n_in,
                              void* d_out, int out_size) {
    const int*   ids  = (const int*)  d_in[0];
    const float* tok  = (const float*)d_in[1];
    const float* pos  = (const float*)d_in[2];
    const float* Wqkv = (const float*)d_in[3];
    const float* bqkv = (const float*)d_in[4];
    const float* Wo   = (const float*)d_in[5];
    const float* bo   = (const float*)d_in[6];
    const float* ln1g = (const float*)d_in[7];
    const float* ln1b = (const float*)d_in[8];
    const float* W1   = (const float*)d_in[9];
    const float* b1   = (const float*)d_in[10];
    const float* W2   = (const float*)d_in[11];
    const float* b2   = (const float*)d_in[12];
    const float* ln2g = (const float*)d_in[13];
    const float* ln2b = (const float*)d_in[14];
    const float* hg   = (const float*)d_in[15];
    const float* hbln = (const float*)d_in[16];
    const float* hW   = (const float*)d_in[17];
    const float* hb   = (const float*)d_in[18];
    float* out = (float*)d_out;

    float *px, *pqkv, *ptmp, *pcls;
    __nv_bfloat16 *pwh, *pwl, *pxh, *pxl, *pah, *pal, *pfh, *pfl;
    cudaGetSymbolAddress((void**)&px,   g_x);
    cudaGetSymbolAddress((void**)&pqkv, g_qkv);
    cudaGetSymbolAddress((void**)&ptmp, g_tmp);
    cudaGetSymbolAddress((void**)&pcls, g_cls);
    cudaGetSymbolAddress((void**)&pwh,  g_wh);
    cudaGetSymbolAddress((void**)&pwl,  g_wl);
    cudaGetSymbolAddress((void**)&pxh,  g_xh);
    cudaGetSymbolAddress((void**)&pxl,  g_xl);
    cudaGetSymbolAddress((void**)&pah,  g_ah);
    cudaGetSymbolAddress((void**)&pal,  g_al);
    cudaGetSymbolAddress((void**)&pfh,  g_fh);
    cudaGetSymbolAddress((void**)&pfl,  g_fl);

    cudaFuncSetAttribute(gemm_mma<0>, cudaFuncAttributeMaxDynamicSharedMemorySize, GSMEM2);
    cudaFuncSetAttribute(gemm_mma<1>, cudaFuncAttributeMaxDynamicSharedMemorySize, GSMEM2);
    cudaFuncSetAttribute(attn_kernel, cudaFuncAttributeMaxDynamicSharedMemorySize, ATTN_SMEM);

    mask_kernel <<<M_ROWS / 256, 256>>>(ids);
    embed_kernel<<<M_ROWS * D_MODEL / 1024, 256>>>(ids, tok, pos);

    // weight conversions (all layers)
    const size_t N_QKV = 3145728, N_WO = 1048576, N_W1 = 4194304, N_W2 = 4194304;
    const size_t WL = N_QKV + N_WO + N_W1 + N_W2;   // 12582912 per layer
    for (int i = 0; i < NLAYER; i++) {
        size_t o_qkv = (size_t)i * WL;
        size_t o_wo  = o_qkv + N_QKV;
        size_t o_w1  = o_wo + N_WO;
        size_t o_w2  = o_w1 + N_W1;
        cvt_kernel<<<(unsigned)(N_QKV/4/256), 256>>>(Wqkv + (size_t)i*N_QKV, pwh + o_qkv, pwl + o_qkv, (int)(N_QKV/4));
        cvt_kernel<<<(unsigned)(N_WO /4/256), 256>>>(Wo   + (size_t)i*N_WO,  pwh + o_wo,  pwl + o_wo,  (int)(N_WO /4));
        cvt_kernel<<<(unsigned)(N_W1 /4/256), 256>>>(W1   + (size_t)i*N_W1,  pwh + o_w1,  pwl + o_w1,  (int)(N_W1 /4));
        cvt_kernel<<<(unsigned)(N_W2 /4/256), 256>>>(W2   + (size_t)i*N_W2,  pwh + o_w2,  pwl + o_w2,  (int)(N_W2 /4));
    }

    for (int i = 0; i < NLAYER; i++) {
        size_t o_qkv = (size_t)i * WL;
        size_t o_wo  = o_qkv + N_QKV;
        size_t o_w1  = o_wo + N_WO;
        size_t o_w2  = o_w1 + N_W1;

        // qkv = x @ Wqkv^T + bqkv   (fp32 out for attention)
        gemm_mma<0><<<dim3(3 * D_MODEL / 128, M_ROWS / 128), 256, GSMEM2>>>(
            pxh, pxl, pwh + o_qkv, pwl + o_qkv, bqkv + (size_t)i * 3 * D_MODEL,
            pqkv, nullptr, nullptr, D_MODEL, 3 * D_MODEL);

        // attention -> g_ah/g_al (bf16 hi/lo)
        attn_kernel<<<dim3(SEQ / 64, NHEAD, BATCH), 256, ATTN_SMEM>>>(pqkv);

        // tmp = attn @ Wo^T + bo
        gemm_mma<0><<<dim3(D_MODEL / 128, M_ROWS / 128), 256, GSMEM2>>>(
            pah, pal, pwh + o_wo, pwl + o_wo, bo + (size_t)i * D_MODEL,
            ptmp, nullptr, nullptr, D_MODEL, D_MODEL);

        // x = ln1(x + tmp)   (+ bf16 hi/lo for FF1)
        ln_kernel<true, true><<<M_ROWS, 256>>>(px, pxh, pxl, px, ptmp,
            ln1g + (size_t)i * D_MODEL, ln1b + (size_t)i * D_MODEL, D_MODEL);

        // ff = gelu(x @ W1^T + b1)  -> bf16 hi/lo
        gemm_mma<1><<<dim3(DIM_FF / 128, M_ROWS / 128), 256, GSMEM2>>>(
            pxh, pxl, pwh + o_w1, pwl + o_w1, b1 + (size_t)i * DIM_FF,
            nullptr, pfh, pfl, D_MODEL, DIM_FF);

        // tmp = ff @ W2^T + b2
        gemm_mma<0><<<dim3(D_MODEL / 128, M_ROWS / 128), 256, GSMEM2>>>(
            pfh, pfl, pwh + o_w2, pwl + o_w2, b2 + (size_t)i * D_MODEL,
            ptmp, nullptr, nullptr, DIM_FF, D_MODEL);

        // x = ln2(x + ff)   (+ bf16 hi/lo for next-layer QKV)
        ln_kernel<true, true><<<M_ROWS, 256>>>(px, pxh, pxl, px, ptmp,
            ln2g + (size_t)i * D_MODEL, ln2b + (size_t)i * D_MODEL, D_MODEL);
    }

    // cls = ln(x[:,0,:]) ; out = cls @ head_W^T + head_b
    ln_kernel<false, false><<<BATCH, 256>>>(pcls, nullptr, nullptr, px, nullptr,
                                            hg, hbln, (size_t)SEQ * D_MODEL);
    head_kernel<<<dim3(D_MODEL / 128, BATCH), 128>>>(out, hW, hb);
}

// round 4
// speedup vs baseline: 2.5702x; 1.5338x over previous
#include <cuda_runtime.h>
#include <cuda_bf16.h>
#include <math.h>
#include <stdint.h>

#define D_MODEL 1024
#define NHEAD   16
#define DH      64
#define NLAYER  6
#define DIM_FF  4096
#define BATCH   8
#define SEQ     1024
#define M_ROWS  (BATCH*SEQ)   // 8192

// ---------------- scratch (static device globals: allocation-free) ----------
__device__ float g_x   [M_ROWS * D_MODEL];      // residual stream (fp32)
__device__ float g_tmp [M_ROWS * D_MODEL];      // GEMM fp32 outputs (Wo / FF2)
__device__ float g_cls [BATCH * D_MODEL];
__device__ unsigned char g_kpm[M_ROWS];

// bf16 hi/lo operand arrays
__device__ __nv_bfloat16 g_wh[75497472];        // all weights hi
__device__ __nv_bfloat16 g_wl[75497472];        // all weights lo
__device__ __nv_bfloat16 g_xh[M_ROWS * D_MODEL];
__device__ __nv_bfloat16 g_xl[M_ROWS * D_MODEL];
__device__ __nv_bfloat16 g_ah[M_ROWS * D_MODEL];
__device__ __nv_bfloat16 g_al[M_ROWS * D_MODEL];
__device__ __nv_bfloat16 g_fh[M_ROWS * DIM_FF];
__device__ __nv_bfloat16 g_fl[M_ROWS * DIM_FF];
// attention operands: q,k [b,h,l,dh]; v transposed [b,h,dh,L]
__device__ __nv_bfloat16 g_qh[M_ROWS * D_MODEL];
__device__ __nv_bfloat16 g_ql[M_ROWS * D_MODEL];
__device__ __nv_bfloat16 g_kh[M_ROWS * D_MODEL];
__device__ __nv_bfloat16 g_kl[M_ROWS * D_MODEL];
__device__ __nv_bfloat16 g_vh[M_ROWS * D_MODEL];
__device__ __nv_bfloat16 g_vl[M_ROWS * D_MODEL];

// ---------------- helpers ----------------------------------------------------
__device__ __forceinline__ uint32_t smem_u32(const void* p) {
    uint32_t a;
    asm("{ .reg .u64 t; cvta.to.shared.u64 t, %1; cvt.u32.u64 %0, t; }"
        : "=r"(a) : "l"(p));
    return a;
}

#define CPA16(dst, src) \
    asm volatile("cp.async.cg.shared.global [%0], [%1], 16;" \
                 :: "r"(dst), "l"(src) : "memory")
#define CPA_COMMIT() asm volatile("cp.async.commit_group;" ::: "memory")
#define CPA_WAIT1()  asm volatile("cp.async.wait_group 1;" ::: "memory")
#define CPA_WAIT0()  asm volatile("cp.async.wait_group 0;" ::: "memory")

#define LDSM4(r, addr) \
    asm volatile("ldmatrix.sync.aligned.m8n8.x4.shared.b16 {%0,%1,%2,%3}, [%4];" \
                 : "=r"((r)[0]), "=r"((r)[1]), "=r"((r)[2]), "=r"((r)[3]) \
                 : "r"(addr))

// bf16 mma m16n8k16, fp32 accumulate
__device__ __forceinline__ void mma16816(float* d, const uint32_t* a, const uint32_t* b) {
    asm volatile(
        "mma.sync.aligned.m16n8k16.row.col.f32.bf16.bf16.f32 "
        "{%0,%1,%2,%3}, {%4,%5,%6,%7}, {%8,%9}, {%0,%1,%2,%3};"
        : "+f"(d[0]), "+f"(d[1]), "+f"(d[2]), "+f"(d[3])
        : "r"(a[0]), "r"(a[1]), "r"(a[2]), "r"(a[3]), "r"(b[0]), "r"(b[1]));
}

__device__ __forceinline__ void split_store(__nv_bfloat16* __restrict__ h,
                                            __nv_bfloat16* __restrict__ l,
                                            size_t off, float v) {
    __nv_bfloat16 hv = __float2bfloat16(v);
    h[off] = hv;
    l[off] = __float2bfloat16(v - __bfloat162float(hv));
}

// ---------------- mask -------------------------------------------------------
__global__ void mask_kernel(const int* __restrict__ ids) {
    int i = blockIdx.x * blockDim.x + threadIdx.x;
    if (i < M_ROWS)
        g_kpm[i] = (ids[i] == 0 && (i & (SEQ - 1)) != 0) ? 1 : 0;
}

// ---------------- embedding --------------------------------------------------
__global__ void embed_kernel(const int* __restrict__ ids,
                             const float* __restrict__ tok,
                             const float* __restrict__ pos) {
    int idx4 = blockIdx.x * blockDim.x + threadIdx.x;
    int base = idx4 << 2;
    int bl   = base >> 10;
    int d    = base & 1023;
    int t    = ids[bl];
    float4 tv = *(const float4*)(tok + (size_t)t * D_MODEL + d);
    float4 pv = *(const float4*)(pos + (size_t)(bl & (SEQ - 1)) * D_MODEL + d);
    float4 o;
    o.x = tv.x + pv.x; o.y = tv.y + pv.y; o.z = tv.z + pv.z; o.w = tv.w + pv.w;
    *(float4*)(g_x + (size_t)base) = o;
    split_store(g_xh, g_xl, base + 0, o.x);
    split_store(g_xh, g_xl, base + 1, o.y);
    split_store(g_xh, g_xl, base + 2, o.z);
    split_store(g_xh, g_xl, base + 3, o.w);
}

// ---------------- weight fp32 -> bf16 hi/lo ---------------------------------
__global__ void cvt_kernel(const float* __restrict__ s,
                           __nv_bfloat16* __restrict__ h,
                           __nv_bfloat16* __restrict__ l, int n4) {
    int i = blockIdx.x * blockDim.x + threadIdx.x;
    if (i >= n4) return;
    float4 v = ((const float4*)s)[i];
    size_t b = (size_t)i << 2;
    split_store(h, l, b + 0, v.x);
    split_store(h, l, b + 1, v.y);
    split_store(h, l, b + 2, v.z);
    split_store(h, l, b + 3, v.w);
}

// ---------------- mma GEMM: C = A @ B^T + bias --------------------------------
// MODE 0: fp32 out. MODE 1: exact GELU -> bf16 hi/lo. MODE 2: QKV split routing.
#define ROWB   80
#define TILEB  (128 * ROWB)
#define STG    (4 * TILEB)
#define GSMEM2 (2 * STG)

template <int MODE>
__global__ void __launch_bounds__(256, 1)
gemm_mma(const __nv_bfloat16* __restrict__ Ah, const __nv_bfloat16* __restrict__ Al,
         const __nv_bfloat16* __restrict__ Bh, const __nv_bfloat16* __restrict__ Bl,
         const float* __restrict__ bias,
         float* __restrict__ Cf,
         __nv_bfloat16* __restrict__ Ch, __nv_bfloat16* __restrict__ Cl,
         int K, int Ntot)
{
    extern __shared__ char sm8[];
    uint32_t sb = smem_u32(sm8);
    int tid = threadIdx.x, wid = tid >> 5, lane = tid & 31;
    int m0 = blockIdx.y << 7, n0 = blockIdx.x << 7;
    int wm = wid & 1, wn = wid >> 1;
    int g = lane >> 2, q = lane & 3;

    int lr = tid >> 2;
    int lcch = tid & 3;

    float acc[4][4][4];
#pragma unroll
    for (int mi = 0; mi < 4; ++mi)
#pragma unroll
        for (int ni = 0; ni < 4; ++ni)
#pragma unroll
            for (int r = 0; r < 4; ++r) acc[mi][ni][r] = 0.f;

    int NC = K >> 5;

    auto load_stage = [&](int s, int c) {
        uint32_t st = sb + s * STG;
        long kb = (long)c << 5;
#pragma unroll
        for (int p = 0; p < 2; ++p) {
            int r = p * 64 + lr;
            uint32_t so = (uint32_t)r * ROWB + lcch * 16;
            CPA16(st + so,             Ah + (size_t)(m0 + r) * K + kb + lcch * 8);
            CPA16(st + TILEB + so,     Al + (size_t)(m0 + r) * K + kb + lcch * 8);
            CPA16(st + 2 * TILEB + so, Bh + (size_t)(n0 + r) * K + kb + lcch * 8);
            CPA16(st + 3 * TILEB + so, Bl + (size_t)(n0 + r) * K + kb + lcch * 8);
        }
    };

    // ldmatrix per-thread row offsets
    uint32_t arow = (uint32_t)(wm * 64 + (lane & 15)) * ROWB + (lane >> 4) * 16;
    uint32_t brow = (uint32_t)(wn * 32 + ((lane >> 4) << 3) + (lane & 7)) * ROWB
                  + ((lane >> 3) & 1) * 16;

    load_stage(0, 0);
    CPA_COMMIT();

    for (int c = 0; c < NC; ++c) {
        if (c + 1 < NC) {
            load_stage((c + 1) & 1, c + 1);
            CPA_COMMIT();
            CPA_WAIT1();
        } else {
            CPA_WAIT0();
        }
        __syncthreads();

        uint32_t base = sb + (uint32_t)(c & 1) * STG;
        uint32_t aHb = base + arow, aLb = aHb + TILEB;
        uint32_t bHb = base + 2 * TILEB + brow, bLb = bHb + TILEB;

#pragma unroll
        for (int ks = 0; ks < 2; ++ks) {
            uint32_t ko = ks * 32;
            uint32_t ah[4][4], al[4][4];
#pragma unroll
            for (int mi = 0; mi < 4; ++mi) {
                LDSM4(ah[mi], aHb + mi * (16 * ROWB) + ko);
                LDSM4(al[mi], aLb + mi * (16 * ROWB) + ko);
            }
#pragma unroll
            for (int nj2 = 0; nj2 < 2; ++nj2) {
                uint32_t bh4[4], bl4[4];
                LDSM4(bh4, bHb + nj2 * (16 * ROWB) + ko);
                LDSM4(bl4, bLb + nj2 * (16 * ROWB) + ko);
#pragma unroll
                for (int half = 0; half < 2; ++half) {
                    int ni = nj2 * 2 + half;
                    uint32_t bhh[2] = {bh4[half * 2], bh4[half * 2 + 1]};
                    uint32_t bll[2] = {bl4[half * 2], bl4[half * 2 + 1]};
#pragma unroll
                    for (int mi = 0; mi < 4; ++mi) {
                        mma16816(acc[mi][ni], ah[mi], bhh);
                        mma16816(acc[mi][ni], ah[mi], bll);
                        mma16816(acc[mi][ni], al[mi], bhh);
                    }
                }
            }
        }
        __syncthreads();
    }

    // ---- epilogue ----
#pragma unroll
    for (int mi = 0; mi < 4; ++mi) {
#pragma unroll
        for (int ni = 0; ni < 4; ++ni) {
            int col = n0 + wn * 32 + ni * 8 + q * 2;
            float2 bv = *(const float2*)(bias + col);
            float* a = acc[mi][ni];
#pragma unroll
            for (int half = 0; half < 2; ++half) {
                int row = m0 + wm * 64 + mi * 16 + g + half * 8;
                float v0 = a[half * 2 + 0] + bv.x;
                float v1 = a[half * 2 + 1] + bv.y;
                if (MODE == 0) {
                    float2 o; o.x = v0; o.y = v1;
                    *(float2*)(Cf + (size_t)row * Ntot + col) = o;
                } else if (MODE == 1) {
                    v0 = 0.5f * v0 * (1.0f + erff(v0 * 0.70710678118654752f));
                    v1 = 0.5f * v1 * (1.0f + erff(v1 * 0.70710678118654752f));
                    __nv_bfloat16 h0 = __float2bfloat16(v0);
                    __nv_bfloat16 h1 = __float2bfloat16(v1);
                    __nv_bfloat162 hp, lp;
                    hp.x = h0; hp.y = h1;
                    lp.x = __float2bfloat16(v0 - __bfloat162float(h0));
                    lp.y = __float2bfloat16(v1 - __bfloat162float(h1));
                    size_t off = (size_t)row * Ntot + col;
                    *(__nv_bfloat162*)(Ch + off) = hp;
                    *(__nv_bfloat162*)(Cl + off) = lp;
                } else {
                    // QKV routing
                    int bb = row >> 10, l = row & 1023;
                    int cat = col >> 10, cc = col & 1023;
                    int hh = cc >> 6, d = cc & 63;
                    __nv_bfloat16 h0 = __float2bfloat16(v0);
                    __nv_bfloat16 h1 = __float2bfloat16(v1);
                    __nv_bfloat16 l0 = __float2bfloat16(v0 - __bfloat162float(h0));
                    __nv_bfloat16 l1 = __float2bfloat16(v1 - __bfloat162float(h1));
                    if (cat < 2) {
                        size_t base2 = (((size_t)bb * NHEAD + hh) * SEQ + l) * DH + d;
                        __nv_bfloat162 hp, lp;
                        hp.x = h0; hp.y = h1; lp.x = l0; lp.y = l1;
                        if (cat == 0) {
                            *(__nv_bfloat162*)(g_qh + base2) = hp;
                            *(__nv_bfloat162*)(g_ql + base2) = lp;
                        } else {
                            *(__nv_bfloat162*)(g_kh + base2) = hp;
                            *(__nv_bfloat162*)(g_kl + base2) = lp;
                        }
                    } else {
                        size_t base2 = (((size_t)bb * NHEAD + hh) * DH + d) * SEQ + l;
                        g_vh[base2] = h0; g_vh[base2 + SEQ] = h1;
                        g_vl[base2] = l0; g_vl[base2 + SEQ] = l1;
                    }
                }
            }
        }
    }
}

// ---------------- tensor-core flash attention --------------------------------
// CTA: 128 queries x (b,h); 8 warps, warp owns 16 query rows.
// K-tiles of 64 keys, 2-stage cp.async pipeline, hi/lo 3-pass MMA.
#define AT_STR   144
#define AT_QB    (128 * AT_STR)          // 18432 per array
#define AT_KVST  (4 * 64 * AT_STR)       // 36864 per stage (Kh,Kl,Vh,Vl)
#define AT_SMEM  (2 * AT_QB + 2 * AT_KVST + 2 * 64 * 4)
#define NKT      (SEQ / 64)              // 16

__global__ void __launch_bounds__(256, 1)
attn_tc() {
    extern __shared__ char sma[];
    uint32_t sb = smem_u32(sma);
    int tid = threadIdx.x, wid = tid >> 5, lane = tid & 31;
    int g = lane >> 2, q = lane & 3;
    int q0 = blockIdx.x << 7;
    int h  = blockIdx.y;
    int b  = blockIdx.z;
    size_t bh = (size_t)b * NHEAD + h;

    const __nv_bfloat16* qhp = g_qh + bh * SEQ * DH;
    const __nv_bfloat16* qlp = g_ql + bh * SEQ * DH;
    const __nv_bfloat16* khp = g_kh + bh * SEQ * DH;
    const __nv_bfloat16* klp = g_kl + bh * SEQ * DH;
    const __nv_bfloat16* vhp = g_vh + bh * DH * SEQ;
    const __nv_bfloat16* vlp = g_vl + bh * DH * SEQ;

    uint32_t sQh = sb, sQl = sb + AT_QB;
    uint32_t sKV0 = sb + 2 * AT_QB;
    float* msks = (float*)(sma + 2 * AT_QB + 2 * AT_KVST);

    // ---- load Q (once) ----
#pragma unroll
    for (int it = 0; it < 4; ++it) {
        int idx = it * 256 + tid;
        int r = idx >> 3, ch = idx & 7;
        uint32_t dst = (uint32_t)r * AT_STR + ch * 16;
        CPA16(sQh + dst, qhp + (size_t)(q0 + r) * DH + ch * 8);
        CPA16(sQl + dst, qlp + (size_t)(q0 + r) * DH + ch * 8);
    }

    auto load_kv = [&](int s, int t) {
        uint32_t st = sKV0 + (uint32_t)s * AT_KVST;
#pragma unroll
        for (int it = 0; it < 2; ++it) {
            int idx = it * 256 + tid;
            int r = idx >> 3, ch = idx & 7;
            uint32_t dst = (uint32_t)r * AT_STR + ch * 16;
            CPA16(st + dst,             khp + (size_t)(t * 64 + r) * DH + ch * 8);
            CPA16(st + 9216 + dst,      klp + (size_t)(t * 64 + r) * DH + ch * 8);
            CPA16(st + 18432 + dst,     vhp + (size_t)r * SEQ + t * 64 + ch * 8);
            CPA16(st + 27648 + dst,     vlp + (size_t)r * SEQ + t * 64 + ch * 8);
        }
        if (tid < 64)
            msks[s * 64 + tid] = g_kpm[b * SEQ + t * 64 + tid] ? 0.f : 1.f;
    };

    load_kv(0, 0);
    CPA_COMMIT();

    // ldmatrix row offsets
    uint32_t qrow = (uint32_t)(wid * 16 + (lane & 15)) * AT_STR + (lane >> 4) * 16;
    uint32_t brow = (uint32_t)(((lane >> 4) << 3) + (lane & 7)) * AT_STR
                  + ((lane >> 3) & 1) * 16;

    uint32_t qfh[4][4], qfl[4][4];
    float cO[8][4];
#pragma unroll
    for (int j = 0; j < 8; ++j)
#pragma unroll
        for (int r = 0; r < 4; ++r) cO[j][r] = 0.f;
    float m0 = -1e30f, m1 = -1e30f, l0 = 0.f, l1 = 0.f;

    for (int t = 0; t < NKT; ++t) {
        int s = t & 1;
        if (t + 1 < NKT) {
            load_kv(s ^ 1, t + 1);
            CPA_COMMIT();
            CPA_WAIT1();
        } else {
            CPA_WAIT0();
        }
        __syncthreads();

        if (t == 0) {
#pragma unroll
            for (int ks = 0; ks < 4; ++ks) {
                LDSM4(qfh[ks], sQh + qrow + ks * 32);
                LDSM4(qfl[ks], sQl + qrow + ks * 32);
            }
        }

        uint32_t kb = sKV0 + (uint32_t)s * AT_KVST;

        // ---- S = Q @ K^T ----
        float cS[8][4];
#pragma unroll
        for (int j = 0; j < 8; ++j)
#pragma unroll
            for (int r = 0; r < 4; ++r) cS[j][r] = 0.f;

#pragma unroll
        for (int ks = 0; ks < 4; ++ks) {
            uint32_t ko = ks * 32;
#pragma unroll
            for (int nj2 = 0; nj2 < 4; ++nj2) {
                uint32_t kh4[4], kl4[4];
                LDSM4(kh4, kb + brow + nj2 * (16 * AT_STR) + ko);
                LDSM4(kl4, kb + 9216 + brow + nj2 * (16 * AT_STR) + ko);
#pragma unroll
                for (int half = 0; half < 2; ++half) {
                    int j = nj2 * 2 + half;
                    uint32_t bhh[2] = {kh4[half * 2], kh4[half * 2 + 1]};
                    uint32_t bll[2] = {kl4[half * 2], kl4[half * 2 + 1]};
                    mma16816(cS[j], qfh[ks], bhh);
                    mma16816(cS[j], qfh[ks], bll);
                    mma16816(cS[j], qfl[ks], bhh);
                }
            }
        }

        // ---- online softmax ----
        float lm0 = -1e30f, lm1 = -1e30f;
#pragma unroll
        for (int j = 0; j < 8; ++j) {
            cS[j][0] *= 0.125f; cS[j][1] *= 0.125f;
            cS[j][2] *= 0.125f; cS[j][3] *= 0.125f;
            lm0 = fmaxf(lm0, fmaxf(cS[j][0], cS[j][1]));
            lm1 = fmaxf(lm1, fmaxf(cS[j][2], cS[j][3]));
        }
        lm0 = fmaxf(lm0, __shfl_xor_sync(0xffffffffu, lm0, 1));
        lm0 = fmaxf(lm0, __shfl_xor_sync(0xffffffffu, lm0, 2));
        lm1 = fmaxf(lm1, __shfl_xor_sync(0xffffffffu, lm1, 1));
        lm1 = fmaxf(lm1, __shfl_xor_sync(0xffffffffu, lm1, 2));
        float mn0 = fmaxf(m0, lm0), mn1 = fmaxf(m1, lm1);
        float a0 = __expf(m0 - mn0), a1 = __expf(m1 - mn1);

        uint32_t PH[8][2], PL[8][2];
        float s0 = 0.f, s1 = 0.f;
#pragma unroll
        for (int j = 0; j < 8; ++j) {
            float mmA = msks[s * 64 + 8 * j + 2 * q];
            float mmB = msks[s * 64 + 8 * j + 2 * q + 1];
            float p0 = __expf(cS[j][0] - mn0) * mmA;
            float p1 = __expf(cS[j][1] - mn0) * mmB;
            float p2 = __expf(cS[j][2] - mn1) * mmA;
            float p3 = __expf(cS[j][3] - mn1) * mmB;
            s0 += p0 + p1; s1 += p2 + p3;
            __nv_bfloat16 h0 = __float2bfloat16(p0), h1 = __float2bfloat16(p1);
            __nv_bfloat16 h2 = __float2bfloat16(p2), h3 = __float2bfloat16(p3);
            PH[j][0] = ((uint32_t)__bfloat16_as_ushort(h1) << 16) | __bfloat16_as_ushort(h0);
            PH[j][1] = ((uint32_t)__bfloat16_as_ushort(h3) << 16) | __bfloat16_as_ushort(h2);
            __nv_bfloat16 e0 = __float2bfloat16(p0 - __bfloat162float(h0));
            __nv_bfloat16 e1 = __float2bfloat16(p1 - __bfloat162float(h1));
            __nv_bfloat16 e2 = __float2bfloat16(p2 - __bfloat162float(h2));
            __nv_bfloat16 e3 = __float2bfloat16(p3 - __bfloat162float(h3));
            PL[j][0] = ((uint32_t)__bfloat16_as_ushort(e1) << 16) | __bfloat16_as_ushort(e0);
            PL[j][1] = ((uint32_t)__bfloat16_as_ushort(e3) << 16) | __bfloat16_as_ushort(e2);
        }
        s0 += __shfl_xor_sync(0xffffffffu, s0, 1);
        s0 += __shfl_xor_sync(0xffffffffu, s0, 2);
        s1 += __shfl_xor_sync(0xffffffffu, s1, 1);
        s1 += __shfl_xor_sync(0xffffffffu, s1, 2);
        l0 = l0 * a0 + s0; l1 = l1 * a1 + s1;
        m0 = mn0; m1 = mn1;

#pragma unroll
        for (int j = 0; j < 8; ++j) {
            cO[j][0] *= a0; cO[j][1] *= a0;
            cO[j][2] *= a1; cO[j][3] *= a1;
        }

        // ---- O += P @ V ----
#pragma unroll
        for (int kk = 0; kk < 4; ++kk) {
            uint32_t ah4[4] = {PH[2*kk][0], PH[2*kk][1], PH[2*kk+1][0], PH[2*kk+1][1]};
            uint32_t al4[4] = {PL[2*kk][0], PL[2*kk][1], PL[2*kk+1][0], PL[2*kk+1][1]};
            uint32_t ko = kk * 32;
#pragma unroll
            for (int nj2 = 0; nj2 < 4; ++nj2) {
                uint32_t vh4[4], vl4[4];
                LDSM4(vh4, kb + 18432 + brow + nj2 * (16 * AT_STR) + ko);
                LDSM4(vl4, kb + 27648 + brow + nj2 * (16 * AT_STR) + ko);
#pragma unroll
                for (int half = 0; half < 2; ++half) {
                    int j = nj2 * 2 + half;
                    uint32_t bhh[2] = {vh4[half * 2], vh4[half * 2 + 1]};
                    uint32_t bll[2] = {vl4[half * 2], vl4[half * 2 + 1]};
                    mma16816(cO[j], ah4, bhh);
                    mma16816(cO[j], ah4, bll);
                    mma16816(cO[j], al4, bhh);
                }
            }
        }
        __syncthreads();
    }

    // ---- write out ----
    float inv0 = 1.0f / l0, inv1 = 1.0f / l1;
    size_t row0 = (size_t)(b * SEQ + q0 + wid * 16 + g);
    size_t row1 = row0 + 8;
#pragma unroll
    for (int j = 0; j < 8; ++j) {
        int col = h * 64 + 8 * j + 2 * q;
        float v0 = cO[j][0] * inv0, v1 = cO[j][1] * inv0;
        float v2 = cO[j][2] * inv1, v3 = cO[j][3] * inv1;
        __nv_bfloat16 h0 = __float2bfloat16(v0), h1 = __float2bfloat16(v1);
        __nv_bfloat16 h2 = __float2bfloat16(v2), h3 = __float2bfloat16(v3);
        __nv_bfloat162 hp0, lp0, hp1, lp1;
        hp0.x = h0; hp0.y = h1;
        lp0.x = __float2bfloat16(v0 - __bfloat162float(h0));
        lp0.y = __float2bfloat16(v1 - __bfloat162float(h1));
        hp1.x = h2; hp1.y = h3;
        lp1.x = __float2bfloat16(v2 - __bfloat162float(h2));
        lp1.y = __float2bfloat16(v3 - __bfloat162float(h3));
        *(__nv_bfloat162*)(g_ah + row0 * D_MODEL + col) = hp0;
        *(__nv_bfloat162*)(g_al + row0 * D_MODEL + col) = lp0;
        *(__nv_bfloat162*)(g_ah + row1 * D_MODEL + col) = hp1;
        *(__nv_bfloat162*)(g_al + row1 * D_MODEL + col) = lp1;
    }
}

// ---------------- LayerNorm (+residual) (+bf16 hi/lo out) -------------------
template <bool HASD, bool WB>
__global__ void ln_kernel(float* __restrict__ out,
                          __nv_bfloat16* __restrict__ oh, __nv_bfloat16* __restrict__ ol,
                          const float* __restrict__ x, const float* __restrict__ delta,
                          const float* __restrict__ g, const float* __restrict__ bta,
                          size_t in_row_stride) {
    __shared__ float vals[D_MODEL];
    __shared__ float red[256];
    __shared__ float red2[256];
    int row = blockIdx.x, tid = threadIdx.x;
    const float* xr = x + (size_t)row * in_row_stride;

    float4 v = *(const float4*)(xr + tid * 4);
    if (HASD) {
        float4 dv = *(const float4*)(delta + (size_t)row * D_MODEL + tid * 4);
        v.x += dv.x; v.y += dv.y; v.z += dv.z; v.w += dv.w;
    }
    *(float4*)&vals[tid * 4] = v;
    red[tid]  = v.x + v.y + v.z + v.w;
    red2[tid] = v.x * v.x + v.y * v.y + v.z * v.z + v.w * v.w;
    __syncthreads();
#pragma unroll
    for (int off = 128; off > 0; off >>= 1) {
        if (tid < off) { red[tid] += red[tid + off]; red2[tid] += red2[tid + off]; }
        __syncthreads();
    }
    float mean = red[0] * (1.0f / D_MODEL);
    float var  = red2[0] * (1.0f / D_MODEL) - mean * mean;
    float inv  = rsqrtf(var + 1e-5f);

    float4 vv = *(float4*)&vals[tid * 4];
    float4 g4 = *(const float4*)(g + tid * 4);
    float4 b4 = *(const float4*)(bta + tid * 4);
    float4 ov;
    ov.x = (vv.x - mean) * inv * g4.x + b4.x;
    ov.y = (vv.y - mean) * inv * g4.y + b4.y;
    ov.z = (vv.z - mean) * inv * g4.z + b4.z;
    ov.w = (vv.w - mean) * inv * g4.w + b4.w;
    size_t base = (size_t)row * D_MODEL + tid * 4;
    *(float4*)(out + base) = ov;
    if (WB) {
        split_store(oh, ol, base + 0, ov.x);
        split_store(oh, ol, base + 1, ov.y);
        split_store(oh, ol, base + 2, ov.z);
        split_store(oh, ol, base + 3, ov.w);
    }
}

// ---------------- head -------------------------------------------------------
__global__ void head_kernel(float* __restrict__ out, const float* __restrict__ W,
                            const float* __restrict__ hb) {
    __shared__ float c[D_MODEL];
    int b = blockIdx.y;
    int n = blockIdx.x * 128 + threadIdx.x;
#pragma unroll
    for (int rep = 0; rep < 2; rep++) {
        int idx = rep * 128 + threadIdx.x;
        *(float4*)&c[idx * 4] = *(const float4*)(g_cls + (size_t)b * D_MODEL + idx * 4);
    }
    __syncthreads();
    const float4* W4 = (const float4*)(W + (size_t)n * D_MODEL);
    const float4* c4 = (const float4*)c;
    float acc = 0.f;
#pragma unroll 8
    for (int k = 0; k < D_MODEL / 4; k++) {
        float4 w = W4[k], cc = c4[k];
        acc += w.x * cc.x + w.y * cc.y + w.z * cc.z + w.w * cc.w;
    }
    out[(size_t)b * D_MODEL + n] = acc + hb[n];
}

// ---------------- launcher ---------------------------------------------------
extern "C" void kernel_launch(void* const* d_in, const int* in_sizes, int n_in,
                              void* d_out, int out_size) {
    const int*   ids  = (const int*)  d_in[0];
    const float* tok  = (const float*)d_in[1];
    const float* pos  = (const float*)d_in[2];
    const float* Wqkv = (const float*)d_in[3];
    const float* bqkv = (const float*)d_in[4];
    const float* Wo   = (const float*)d_in[5];
    const float* bo   = (const float*)d_in[6];
    const float* ln1g = (const float*)d_in[7];
    const float* ln1b = (const float*)d_in[8];
    const float* W1   = (const float*)d_in[9];
    const float* b1   = (const float*)d_in[10];
    const float* W2   = (const float*)d_in[11];
    const float* b2   = (const float*)d_in[12];
    const float* ln2g = (const float*)d_in[13];
    const float* ln2b = (const float*)d_in[14];
    const float* hg   = (const float*)d_in[15];
    const float* hbln = (const float*)d_in[16];
    const float* hW   = (const float*)d_in[17];
    const float* hb   = (const float*)d_in[18];
    float* out = (float*)d_out;

    float *px, *ptmp, *pcls;
    __nv_bfloat16 *pwh, *pwl, *pxh, *pxl, *pah, *pal, *pfh, *pfl;
    cudaGetSymbolAddress((void**)&px,   g_x);
    cudaGetSymbolAddress((void**)&ptmp, g_tmp);
    cudaGetSymbolAddress((void**)&pcls, g_cls);
    cudaGetSymbolAddress((void**)&pwh,  g_wh);
    cudaGetSymbolAddress((void**)&pwl,  g_wl);
    cudaGetSymbolAddress((void**)&pxh,  g_xh);
    cudaGetSymbolAddress((void**)&pxl,  g_xl);
    cudaGetSymbolAddress((void**)&pah,  g_ah);
    cudaGetSymbolAddress((void**)&pal,  g_al);
    cudaGetSymbolAddress((void**)&pfh,  g_fh);
    cudaGetSymbolAddress((void**)&pfl,  g_fl);

    cudaFuncSetAttribute(gemm_mma<0>, cudaFuncAttributeMaxDynamicSharedMemorySize, GSMEM2);
    cudaFuncSetAttribute(gemm_mma<1>, cudaFuncAttributeMaxDynamicSharedMemorySize, GSMEM2);
    cudaFuncSetAttribute(gemm_mma<2>, cudaFuncAttributeMaxDynamicSharedMemorySize, GSMEM2);
    cudaFuncSetAttribute(attn_tc, cudaFuncAttributeMaxDynamicSharedMemorySize, AT_SMEM);

    mask_kernel <<<M_ROWS / 256, 256>>>(ids);
    embed_kernel<<<M_ROWS * D_MODEL / 1024, 256>>>(ids, tok, pos);

    const size_t N_QKV = 3145728, N_WO = 1048576, N_W1 = 4194304, N_W2 = 4194304;
    const size_t WL = N_QKV + N_WO + N_W1 + N_W2;
    for (int i = 0; i < NLAYER; i++) {
        size_t o_qkv = (size_t)i * WL;
        size_t o_wo  = o_qkv + N_QKV;
        size_t o_w1  = o_wo + N_WO;
        size_t o_w2  = o_w1 + N_W1;
        cvt_kernel<<<(unsigned)(N_QKV/4/256), 256>>>(Wqkv + (size_t)i*N_QKV, pwh + o_qkv, pwl + o_qkv, (int)(N_QKV/4));
        cvt_kernel<<<(unsigned)(N_WO /4/256), 256>>>(Wo   + (size_t)i*N_WO,  pwh + o_wo,  pwl + o_wo,  (int)(N_WO /4));
        cvt_kernel<<<(unsigned)(N_W1 /4/256), 256>>>(W1   + (size_t)i*N_W1,  pwh + o_w1,  pwl + o_w1,  (int)(N_W1 /4));
        cvt_kernel<<<(unsigned)(N_W2 /4/256), 256>>>(W2   + (size_t)i*N_W2,  pwh + o_w2,  pwl + o_w2,  (int)(N_W2 /4));
    }

    for (int i = 0; i < NLAYER; i++) {
        size_t o_qkv = (size_t)i * WL;
        size_t o_wo  = o_qkv + N_QKV;
        size_t o_w1  = o_wo + N_WO;
        size_t o_w2  = o_w1 + N_W1;

        // qkv = x @ Wqkv^T + bqkv  -> split q/k/v bf16 hi/lo (v transposed)
        gemm_mma<2><<<dim3(3 * D_MODEL / 128, M_ROWS / 128), 256, GSMEM2>>>(
            pxh, pxl, pwh + o_qkv, pwl + o_qkv, bqkv + (size_t)i * 3 * D_MODEL,
            nullptr, nullptr, nullptr, D_MODEL, 3 * D_MODEL);

        // attention -> g_ah/g_al
        attn_tc<<<dim3(SEQ / 128, NHEAD, BATCH), 256, AT_SMEM>>>();

        // tmp = attn @ Wo^T + bo
        gemm_mma<0><<<dim3(D_MODEL / 128, M_ROWS / 128), 256, GSMEM2>>>(
            pah, pal, pwh + o_wo, pwl + o_wo, bo + (size_t)i * D_MODEL,
            ptmp, nullptr, nullptr, D_MODEL, D_MODEL);

        // x = ln1(x + tmp)
        ln_kernel<true, true><<<M_ROWS, 256>>>(px, pxh, pxl, px, ptmp,
            ln1g + (size_t)i * D_MODEL, ln1b + (size_t)i * D_MODEL, D_MODEL);

        // ff = gelu(x @ W1^T + b1) -> bf16 hi/lo
        gemm_mma<1><<<dim3(DIM_FF / 128, M_ROWS / 128), 256, GSMEM2>>>(
            pxh, pxl, pwh + o_w1, pwl + o_w1, b1 + (size_t)i * DIM_FF,
            nullptr, pfh, pfl, D_MODEL, DIM_FF);

        // tmp = ff @ W2^T + b2
        gemm_mma<0><<<dim3(D_MODEL / 128, M_ROWS / 128), 256, GSMEM2>>>(
            pfh, pfl, pwh + o_w2, pwl + o_w2, b2 + (size_t)i * D_MODEL,
            ptmp, nullptr, nullptr, DIM_FF, D_MODEL);

        // x = ln2(x + ff)
        ln_kernel<true, true><<<M_ROWS, 256>>>(px, pxh, pxl, px, ptmp,
            ln2g + (size_t)i * D_MODEL, ln2b + (size_t)i * D_MODEL, D_MODEL);
    }

    ln_kernel<false, false><<<BATCH, 256>>>(pcls, nullptr, nullptr, px, nullptr,
                                            hg, hbln, (size_t)SEQ * D_MODEL);
    head_kernel<<<dim3(D_MODEL / 128, BATCH), 128>>>(out, hW, hb);
}

// round 5
// speedup vs baseline: 2.8351x; 1.1031x over previous
#include <cuda_runtime.h>
#include <cuda_bf16.h>
#include <math.h>
#include <stdint.h>

#define D_MODEL 1024
#define NHEAD   16
#define DH      64
#define NLAYER  6
#define DIM_FF  4096
#define BATCH   8
#define SEQ     1024
#define M_ROWS  (BATCH*SEQ)   // 8192

// ---------------- scratch ----------------
__device__ float g_x   [M_ROWS * D_MODEL];
__device__ float g_tmp [M_ROWS * D_MODEL];
__device__ float g_cls [BATCH * D_MODEL];
__device__ unsigned char g_kpm[M_ROWS];

__device__ __nv_bfloat16 g_wh[75497472];
__device__ __nv_bfloat16 g_wl[75497472];
__device__ __nv_bfloat16 g_xh[M_ROWS * D_MODEL];
__device__ __nv_bfloat16 g_xl[M_ROWS * D_MODEL];
__device__ __nv_bfloat16 g_ah[M_ROWS * D_MODEL];
__device__ __nv_bfloat16 g_al[M_ROWS * D_MODEL];
__device__ __nv_bfloat16 g_fh[M_ROWS * DIM_FF];
__device__ __nv_bfloat16 g_fl[M_ROWS * DIM_FF];
__device__ __nv_bfloat16 g_qh[M_ROWS * D_MODEL];
__device__ __nv_bfloat16 g_ql[M_ROWS * D_MODEL];
__device__ __nv_bfloat16 g_kh[M_ROWS * D_MODEL];
__device__ __nv_bfloat16 g_kl[M_ROWS * D_MODEL];
__device__ __nv_bfloat16 g_vh[M_ROWS * D_MODEL];
__device__ __nv_bfloat16 g_vl[M_ROWS * D_MODEL];

// ---------------- helpers ----------------
__device__ __forceinline__ uint32_t smem_u32(const void* p) {
    uint32_t a;
    asm("{ .reg .u64 t; cvta.to.shared.u64 t, %1; cvt.u32.u64 %0, t; }"
        : "=r"(a) : "l"(p));
    return a;
}

#define CPA16(dst, src) \
    asm volatile("cp.async.cg.shared.global [%0], [%1], 16;" \
                 :: "r"(dst), "l"(src) : "memory")
#define CPA_COMMIT() asm volatile("cp.async.commit_group;" ::: "memory")
#define CPA_WAIT1()  asm volatile("cp.async.wait_group 1;" ::: "memory")
#define CPA_WAIT0()  asm volatile("cp.async.wait_group 0;" ::: "memory")

#define LDSM4(r, addr) \
    asm volatile("ldmatrix.sync.aligned.m8n8.x4.shared.b16 {%0,%1,%2,%3}, [%4];" \
                 : "=r"((r)[0]), "=r"((r)[1]), "=r"((r)[2]), "=r"((r)[3]) \
                 : "r"(addr))

__device__ __forceinline__ void mma16816(float* d, const uint32_t* a, const uint32_t* b) {
    asm volatile(
        "mma.sync.aligned.m16n8k16.row.col.f32.bf16.bf16.f32 "
        "{%0,%1,%2,%3}, {%4,%5,%6,%7}, {%8,%9}, {%0,%1,%2,%3};"
        : "+f"(d[0]), "+f"(d[1]), "+f"(d[2]), "+f"(d[3])
        : "r"(a[0]), "r"(a[1]), "r"(a[2]), "r"(a[3]), "r"(b[0]), "r"(b[1]));
}

__device__ __forceinline__ uint32_t pack2(float v0, float v1,
                                          float& r0, float& r1) {
    __nv_bfloat16 h0 = __float2bfloat16(v0);
    __nv_bfloat16 h1 = __float2bfloat16(v1);
    r0 = v0 - __bfloat162float(h0);
    r1 = v1 - __bfloat162float(h1);
    return ((uint32_t)__bfloat16_as_ushort(h1) << 16) | __bfloat16_as_ushort(h0);
}
__device__ __forceinline__ uint32_t pack2lo(float r0, float r1) {
    __nv_bfloat16 e0 = __float2bfloat16(r0);
    __nv_bfloat16 e1 = __float2bfloat16(r1);
    return ((uint32_t)__bfloat16_as_ushort(e1) << 16) | __bfloat16_as_ushort(e0);
}

__device__ __forceinline__ void split_store(__nv_bfloat16* __restrict__ h,
                                            __nv_bfloat16* __restrict__ l,
                                            size_t off, float v) {
    __nv_bfloat16 hv = __float2bfloat16(v);
    h[off] = hv;
    l[off] = __float2bfloat16(v - __bfloat162float(hv));
}

// ---------------- mask ----------------
__global__ void mask_kernel(const int* __restrict__ ids) {
    int i = blockIdx.x * blockDim.x + threadIdx.x;
    if (i < M_ROWS)
        g_kpm[i] = (ids[i] == 0 && (i & (SEQ - 1)) != 0) ? 1 : 0;
}

// ---------------- embedding ----------------
__global__ void embed_kernel(const int* __restrict__ ids,
                             const float* __restrict__ tok,
                             const float* __restrict__ pos) {
    int idx4 = blockIdx.x * blockDim.x + threadIdx.x;
    int base = idx4 << 2;
    int bl   = base >> 10;
    int d    = base & 1023;
    int t    = ids[bl];
    float4 tv = *(const float4*)(tok + (size_t)t * D_MODEL + d);
    float4 pv = *(const float4*)(pos + (size_t)(bl & (SEQ - 1)) * D_MODEL + d);
    float4 o;
    o.x = tv.x + pv.x; o.y = tv.y + pv.y; o.z = tv.z + pv.z; o.w = tv.w + pv.w;
    *(float4*)(g_x + (size_t)base) = o;
    float r0, r1, r2, r3;
    uint2 hp, lp;
    hp.x = pack2(o.x, o.y, r0, r1);
    hp.y = pack2(o.z, o.w, r2, r3);
    lp.x = pack2lo(r0, r1);
    lp.y = pack2lo(r2, r3);
    *(uint2*)(g_xh + base) = hp;
    *(uint2*)(g_xl + base) = lp;
}

// ---------------- weight fp32 -> bf16 hi/lo (vectorized, 8 el/thread) -------
__global__ void cvt_kernel(const float* __restrict__ s,
                           __nv_bfloat16* __restrict__ h,
                           __nv_bfloat16* __restrict__ l, int n8) {
    int i = blockIdx.x * blockDim.x + threadIdx.x;
    if (i >= n8) return;
    float4 v0 = ((const float4*)s)[2 * i];
    float4 v1 = ((const float4*)s)[2 * i + 1];
    float r[8];
    uint4 hv, lv;
    hv.x = pack2(v0.x, v0.y, r[0], r[1]);
    hv.y = pack2(v0.z, v0.w, r[2], r[3]);
    hv.z = pack2(v1.x, v1.y, r[4], r[5]);
    hv.w = pack2(v1.z, v1.w, r[6], r[7]);
    lv.x = pack2lo(r[0], r[1]);
    lv.y = pack2lo(r[2], r[3]);
    lv.z = pack2lo(r[4], r[5]);
    lv.w = pack2lo(r[6], r[7]);
    ((uint4*)h)[i] = hv;
    ((uint4*)l)[i] = lv;
}

// ---------------- mma GEMM: C = A @ B^T + bias --------------------------------
// CTA tile 256x128, BK=32, warp tile 64x64, 8 warps (4 M x 2 N), 256 threads.
// MODE 0: fp32 out. MODE 1: exact GELU -> bf16 hi/lo. MODE 2: QKV split routing.
#define ROWB   80
#define ATILE  (256 * ROWB)     // 20480
#define BTILE  (128 * ROWB)     // 10240
#define STG    (2 * ATILE + 2 * BTILE)  // 61440
#define GSMEM2 (2 * STG)                // 122880

template <int MODE>
__global__ void __launch_bounds__(256, 1)
gemm_mma(const __nv_bfloat16* __restrict__ Ah, const __nv_bfloat16* __restrict__ Al,
         const __nv_bfloat16* __restrict__ Bh, const __nv_bfloat16* __restrict__ Bl,
         const float* __restrict__ bias,
         float* __restrict__ Cf,
         __nv_bfloat16* __restrict__ Ch, __nv_bfloat16* __restrict__ Cl,
         int K, int Ntot)
{
    extern __shared__ char sm8[];
    uint32_t sb = smem_u32(sm8);
    int tid = threadIdx.x, wid = tid >> 5, lane = tid & 31;
    int m0 = blockIdx.y << 8, n0 = blockIdx.x << 7;
    int wm = wid & 3, wn = wid >> 2;       // warp grid 4 (M) x 2 (N)
    int g = lane >> 2, q = lane & 3;

    float acc[4][8][4];
#pragma unroll
    for (int mi = 0; mi < 4; ++mi)
#pragma unroll
        for (int ni = 0; ni < 8; ++ni)
#pragma unroll
            for (int r = 0; r < 4; ++r) acc[mi][ni][r] = 0.f;

    int NC = K >> 5;

    auto load_stage = [&](int s, int c) {
        uint32_t st = sb + s * STG;
        long kb = (long)c << 5;
#pragma unroll
        for (int it = 0; it < 4; ++it) {            // A: 256 rows x 4 chunks
            int idx = it * 256 + tid;
            int r = idx >> 2, ch = idx & 3;
            uint32_t so = (uint32_t)r * ROWB + ch * 16;
            CPA16(st + so,         Ah + (size_t)(m0 + r) * K + kb + ch * 8);
            CPA16(st + ATILE + so, Al + (size_t)(m0 + r) * K + kb + ch * 8);
        }
#pragma unroll
        for (int it = 0; it < 2; ++it) {            // B: 128 rows x 4 chunks
            int idx = it * 256 + tid;
            int r = idx >> 2, ch = idx & 3;
            uint32_t so = (uint32_t)r * ROWB + ch * 16;
            CPA16(st + 2 * ATILE + so,         Bh + (size_t)(n0 + r) * K + kb + ch * 8);
            CPA16(st + 2 * ATILE + BTILE + so, Bl + (size_t)(n0 + r) * K + kb + ch * 8);
        }
    };

    uint32_t arow = (uint32_t)(wm * 64 + (lane & 15)) * ROWB + (lane >> 4) * 16;
    uint32_t brow = (uint32_t)(wn * 64 + ((lane >> 4) << 3) + (lane & 7)) * ROWB
                  + ((lane >> 3) & 1) * 16;

    load_stage(0, 0);
    CPA_COMMIT();

    for (int c = 0; c < NC; ++c) {
        if (c + 1 < NC) {
            load_stage((c + 1) & 1, c + 1);
            CPA_COMMIT();
            CPA_WAIT1();
        } else {
            CPA_WAIT0();
        }
        __syncthreads();

        uint32_t base = sb + (uint32_t)(c & 1) * STG;
        uint32_t aHb = base + arow, aLb = aHb + ATILE;
        uint32_t bHb = base + 2 * ATILE + brow, bLb = bHb + BTILE;

#pragma unroll
        for (int ks = 0; ks < 2; ++ks) {
            uint32_t ko = ks * 32;
            uint32_t ah[4][4], al[4][4];
#pragma unroll
            for (int mi = 0; mi < 4; ++mi) {
                LDSM4(ah[mi], aHb + mi * (16 * ROWB) + ko);
                LDSM4(al[mi], aLb + mi * (16 * ROWB) + ko);
            }
#pragma unroll
            for (int nj2 = 0; nj2 < 4; ++nj2) {
                uint32_t bh4[4], bl4[4];
                LDSM4(bh4, bHb + nj2 * (16 * ROWB) + ko);
                LDSM4(bl4, bLb + nj2 * (16 * ROWB) + ko);
#pragma unroll
                for (int half = 0; half < 2; ++half) {
                    int ni = nj2 * 2 + half;
                    uint32_t bhh[2] = {bh4[half * 2], bh4[half * 2 + 1]};
                    uint32_t bll[2] = {bl4[half * 2], bl4[half * 2 + 1]};
#pragma unroll
                    for (int mi = 0; mi < 4; ++mi) {
                        mma16816(acc[mi][ni], ah[mi], bhh);
                        mma16816(acc[mi][ni], ah[mi], bll);
                        mma16816(acc[mi][ni], al[mi], bhh);
                    }
                }
            }
        }
        __syncthreads();
    }

    // ---- epilogue ----
#pragma unroll
    for (int mi = 0; mi < 4; ++mi) {
#pragma unroll
        for (int ni = 0; ni < 8; ++ni) {
            int col = n0 + wn * 64 + ni * 8 + q * 2;
            float2 bv = *(const float2*)(bias + col);
            float* a = acc[mi][ni];
#pragma unroll
            for (int half = 0; half < 2; ++half) {
                int row = m0 + wm * 64 + mi * 16 + g + half * 8;
                float v0 = a[half * 2 + 0] + bv.x;
                float v1 = a[half * 2 + 1] + bv.y;
                if (MODE == 0) {
                    float2 o; o.x = v0; o.y = v1;
                    *(float2*)(Cf + (size_t)row * Ntot + col) = o;
                } else if (MODE == 1) {
                    v0 = 0.5f * v0 * (1.0f + erff(v0 * 0.70710678118654752f));
                    v1 = 0.5f * v1 * (1.0f + erff(v1 * 0.70710678118654752f));
                    float r0, r1;
                    uint32_t hp = pack2(v0, v1, r0, r1);
                    uint32_t lp = pack2lo(r0, r1);
                    size_t off = (size_t)row * Ntot + col;
                    *(uint32_t*)(Ch + off) = hp;
                    *(uint32_t*)(Cl + off) = lp;
                } else {
                    int bb = row >> 10, l = row & 1023;
                    int cat = col >> 10, cc = col & 1023;
                    int hh = cc >> 6, d = cc & 63;
                    float r0, r1;
                    uint32_t hp = pack2(v0, v1, r0, r1);
                    uint32_t lp = pack2lo(r0, r1);
                    if (cat < 2) {
                        size_t base2 = (((size_t)bb * NHEAD + hh) * SEQ + l) * DH + d;
                        if (cat == 0) {
                            *(uint32_t*)(g_qh + base2) = hp;
                            *(uint32_t*)(g_ql + base2) = lp;
                        } else {
                            *(uint32_t*)(g_kh + base2) = hp;
                            *(uint32_t*)(g_kl + base2) = lp;
                        }
                    } else {
                        size_t base2 = (((size_t)bb * NHEAD + hh) * DH + d) * SEQ + l;
                        __nv_bfloat16 h0 = __ushort_as_bfloat16((unsigned short)(hp & 0xffff));
                        __nv_bfloat16 h1 = __ushort_as_bfloat16((unsigned short)(hp >> 16));
                        __nv_bfloat16 l0 = __ushort_as_bfloat16((unsigned short)(lp & 0xffff));
                        __nv_bfloat16 l1 = __ushort_as_bfloat16((unsigned short)(lp >> 16));
                        g_vh[base2] = h0; g_vh[base2 + SEQ] = h1;
                        g_vl[base2] = l0; g_vl[base2 + SEQ] = l1;
                    }
                }
            }
        }
    }
}

// ---------------- tensor-core flash attention --------------------------------
#define AT_STR   144
#define AT_QB    (128 * AT_STR)
#define AT_KVST  (4 * 64 * AT_STR)
#define AT_SMEM  (2 * AT_QB + 2 * AT_KVST + 2 * 64 * 4)
#define NKT      (SEQ / 64)

__global__ void __launch_bounds__(256, 1)
attn_tc() {
    extern __shared__ char sma[];
    uint32_t sb = smem_u32(sma);
    int tid = threadIdx.x, wid = tid >> 5, lane = tid & 31;
    int g = lane >> 2, q = lane & 3;
    int q0 = blockIdx.x << 7;
    int h  = blockIdx.y;
    int b  = blockIdx.z;
    size_t bh = (size_t)b * NHEAD + h;

    const __nv_bfloat16* qhp = g_qh + bh * SEQ * DH;
    const __nv_bfloat16* qlp = g_ql + bh * SEQ * DH;
    const __nv_bfloat16* khp = g_kh + bh * SEQ * DH;
    const __nv_bfloat16* klp = g_kl + bh * SEQ * DH;
    const __nv_bfloat16* vhp = g_vh + bh * DH * SEQ;
    const __nv_bfloat16* vlp = g_vl + bh * DH * SEQ;

    uint32_t sQh = sb, sQl = sb + AT_QB;
    uint32_t sKV0 = sb + 2 * AT_QB;
    float* msks = (float*)(sma + 2 * AT_QB + 2 * AT_KVST);

#pragma unroll
    for (int it = 0; it < 4; ++it) {
        int idx = it * 256 + tid;
        int r = idx >> 3, ch = idx & 7;
        uint32_t dst = (uint32_t)r * AT_STR + ch * 16;
        CPA16(sQh + dst, qhp + (size_t)(q0 + r) * DH + ch * 8);
        CPA16(sQl + dst, qlp + (size_t)(q0 + r) * DH + ch * 8);
    }

    auto load_kv = [&](int s, int t) {
        uint32_t st = sKV0 + (uint32_t)s * AT_KVST;
#pragma unroll
        for (int it = 0; it < 2; ++it) {
            int idx = it * 256 + tid;
            int r = idx >> 3, ch = idx & 7;
            uint32_t dst = (uint32_t)r * AT_STR + ch * 16;
            CPA16(st + dst,         khp + (size_t)(t * 64 + r) * DH + ch * 8);
            CPA16(st + 9216 + dst,  klp + (size_t)(t * 64 + r) * DH + ch * 8);
            CPA16(st + 18432 + dst, vhp + (size_t)r * SEQ + t * 64 + ch * 8);
            CPA16(st + 27648 + dst, vlp + (size_t)r * SEQ + t * 64 + ch * 8);
        }
        if (tid < 64)
            msks[s * 64 + tid] = g_kpm[b * SEQ + t * 64 + tid] ? 0.f : 1.f;
    };

    load_kv(0, 0);
    CPA_COMMIT();

    uint32_t qrow = (uint32_t)(wid * 16 + (lane & 15)) * AT_STR + (lane >> 4) * 16;
    uint32_t brow = (uint32_t)(((lane >> 4) << 3) + (lane & 7)) * AT_STR
                  + ((lane >> 3) & 1) * 16;

    uint32_t qfh[4][4], qfl[4][4];
    float cO[8][4];
#pragma unroll
    for (int j = 0; j < 8; ++j)
#pragma unroll
        for (int r = 0; r < 4; ++r) cO[j][r] = 0.f;
    float m0 = -1e30f, m1 = -1e30f, l0 = 0.f, l1 = 0.f;

    for (int t = 0; t < NKT; ++t) {
        int s = t & 1;
        if (t + 1 < NKT) {
            load_kv(s ^ 1, t + 1);
            CPA_COMMIT();
            CPA_WAIT1();
        } else {
            CPA_WAIT0();
        }
        __syncthreads();

        if (t == 0) {
#pragma unroll
            for (int ks = 0; ks < 4; ++ks) {
                LDSM4(qfh[ks], sQh + qrow + ks * 32);
                LDSM4(qfl[ks], sQl + qrow + ks * 32);
            }
        }

        uint32_t kb = sKV0 + (uint32_t)s * AT_KVST;

        float cS[8][4];
#pragma unroll
        for (int j = 0; j < 8; ++j)
#pragma unroll
            for (int r = 0; r < 4; ++r) cS[j][r] = 0.f;

#pragma unroll
        for (int ks = 0; ks < 4; ++ks) {
            uint32_t ko = ks * 32;
#pragma unroll
            for (int nj2 = 0; nj2 < 4; ++nj2) {
                uint32_t kh4[4], kl4[4];
                LDSM4(kh4, kb + brow + nj2 * (16 * AT_STR) + ko);
                LDSM4(kl4, kb + 9216 + brow + nj2 * (16 * AT_STR) + ko);
#pragma unroll
                for (int half = 0; half < 2; ++half) {
                    int j = nj2 * 2 + half;
                    uint32_t bhh[2] = {kh4[half * 2], kh4[half * 2 + 1]};
                    uint32_t bll[2] = {kl4[half * 2], kl4[half * 2 + 1]};
                    mma16816(cS[j], qfh[ks], bhh);
                    mma16816(cS[j], qfh[ks], bll);
                    mma16816(cS[j], qfl[ks], bhh);
                }
            }
        }

        float lm0 = -1e30f, lm1 = -1e30f;
#pragma unroll
        for (int j = 0; j < 8; ++j) {
            cS[j][0] *= 0.125f; cS[j][1] *= 0.125f;
            cS[j][2] *= 0.125f; cS[j][3] *= 0.125f;
            lm0 = fmaxf(lm0, fmaxf(cS[j][0], cS[j][1]));
            lm1 = fmaxf(lm1, fmaxf(cS[j][2], cS[j][3]));
        }
        lm0 = fmaxf(lm0, __shfl_xor_sync(0xffffffffu, lm0, 1));
        lm0 = fmaxf(lm0, __shfl_xor_sync(0xffffffffu, lm0, 2));
        lm1 = fmaxf(lm1, __shfl_xor_sync(0xffffffffu, lm1, 1));
        lm1 = fmaxf(lm1, __shfl_xor_sync(0xffffffffu, lm1, 2));
        float mn0 = fmaxf(m0, lm0), mn1 = fmaxf(m1, lm1);
        float a0 = __expf(m0 - mn0), a1 = __expf(m1 - mn1);

        uint32_t PH[8][2], PL[8][2];
        float s0 = 0.f, s1 = 0.f;
#pragma unroll
        for (int j = 0; j < 8; ++j) {
            float mmA = msks[s * 64 + 8 * j + 2 * q];
            float mmB = msks[s * 64 + 8 * j + 2 * q + 1];
            float p0 = __expf(cS[j][0] - mn0) * mmA;
            float p1 = __expf(cS[j][1] - mn0) * mmB;
            float p2 = __expf(cS[j][2] - mn1) * mmA;
            float p3 = __expf(cS[j][3] - mn1) * mmB;
            s0 += p0 + p1; s1 += p2 + p3;
            float r0, r1, r2, r3;
            PH[j][0] = pack2(p0, p1, r0, r1);
            PH[j][1] = pack2(p2, p3, r2, r3);
            PL[j][0] = pack2lo(r0, r1);
            PL[j][1] = pack2lo(r2, r3);
        }
        s0 += __shfl_xor_sync(0xffffffffu, s0, 1);
        s0 += __shfl_xor_sync(0xffffffffu, s0, 2);
        s1 += __shfl_xor_sync(0xffffffffu, s1, 1);
        s1 += __shfl_xor_sync(0xffffffffu, s1, 2);
        l0 = l0 * a0 + s0; l1 = l1 * a1 + s1;
        m0 = mn0; m1 = mn1;

#pragma unroll
        for (int j = 0; j < 8; ++j) {
            cO[j][0] *= a0; cO[j][1] *= a0;
            cO[j][2] *= a1; cO[j][3] *= a1;
        }

#pragma unroll
        for (int kk = 0; kk < 4; ++kk) {
            uint32_t ah4[4] = {PH[2*kk][0], PH[2*kk][1], PH[2*kk+1][0], PH[2*kk+1][1]};
            uint32_t al4[4] = {PL[2*kk][0], PL[2*kk][1], PL[2*kk+1][0], PL[2*kk+1][1]};
            uint32_t ko = kk * 32;
#pragma unroll
            for (int nj2 = 0; nj2 < 4; ++nj2) {
                uint32_t vh4[4], vl4[4];
                LDSM4(vh4, kb + 18432 + brow + nj2 * (16 * AT_STR) + ko);
                LDSM4(vl4, kb + 27648 + brow + nj2 * (16 * AT_STR) + ko);
#pragma unroll
                for (int half = 0; half < 2; ++half) {
                    int j = nj2 * 2 + half;
                    uint32_t bhh[2] = {vh4[half * 2], vh4[half * 2 + 1]};
                    uint32_t bll[2] = {vl4[half * 2], vl4[half * 2 + 1]};
                    mma16816(cO[j], ah4, bhh);
                    mma16816(cO[j], ah4, bll);
                    mma16816(cO[j], al4, bhh);
                }
            }
        }
        __syncthreads();
    }

    float inv0 = 1.0f / l0, inv1 = 1.0f / l1;
    size_t row0 = (size_t)(b * SEQ + q0 + wid * 16 + g);
    size_t row1 = row0 + 8;
#pragma unroll
    for (int j = 0; j < 8; ++j) {
        int col = h * 64 + 8 * j + 2 * q;
        float r0, r1, r2, r3;
        uint32_t hp0 = pack2(cO[j][0] * inv0, cO[j][1] * inv0, r0, r1);
        uint32_t hp1 = pack2(cO[j][2] * inv1, cO[j][3] * inv1, r2, r3);
        uint32_t lp0 = pack2lo(r0, r1);
        uint32_t lp1 = pack2lo(r2, r3);
        *(uint32_t*)(g_ah + row0 * D_MODEL + col) = hp0;
        *(uint32_t*)(g_al + row0 * D_MODEL + col) = lp0;
        *(uint32_t*)(g_ah + row1 * D_MODEL + col) = hp1;
        *(uint32_t*)(g_al + row1 * D_MODEL + col) = lp1;
    }
}

// ---------------- LayerNorm (+residual) (+bf16 hi/lo out) -------------------
template <bool HASD, bool WB>
__global__ void ln_kernel(float* __restrict__ out,
                          __nv_bfloat16* __restrict__ oh, __nv_bfloat16* __restrict__ ol,
                          const float* __restrict__ x, const float* __restrict__ delta,
                          const float* __restrict__ g, const float* __restrict__ bta,
                          size_t in_row_stride) {
    __shared__ float vals[D_MODEL];
    __shared__ float red[256];
    __shared__ float red2[256];
    int row = blockIdx.x, tid = threadIdx.x;
    const float* xr = x + (size_t)row * in_row_stride;

    float4 v = *(const float4*)(xr + tid * 4);
    if (HASD) {
        float4 dv = *(const float4*)(delta + (size_t)row * D_MODEL + tid * 4);
        v.x += dv.x; v.y += dv.y; v.z += dv.z; v.w += dv.w;
    }
    *(float4*)&vals[tid * 4] = v;
    red[tid]  = v.x + v.y + v.z + v.w;
    red2[tid] = v.x * v.x + v.y * v.y + v.z * v.z + v.w * v.w;
    __syncthreads();
#pragma unroll
    for (int off = 128; off > 0; off >>= 1) {
        if (tid < off) { red[tid] += red[tid + off]; red2[tid] += red2[tid + off]; }
        __syncthreads();
    }
    float mean = red[0] * (1.0f / D_MODEL);
    float var  = red2[0] * (1.0f / D_MODEL) - mean * mean;
    float inv  = rsqrtf(var + 1e-5f);

    float4 vv = *(float4*)&vals[tid * 4];
    float4 g4 = *(const float4*)(g + tid * 4);
    float4 b4 = *(const float4*)(bta + tid * 4);
    float4 ov;
    ov.x = (vv.x - mean) * inv * g4.x + b4.x;
    ov.y = (vv.y - mean) * inv * g4.y + b4.y;
    ov.z = (vv.z - mean) * inv * g4.z + b4.z;
    ov.w = (vv.w - mean) * inv * g4.w + b4.w;
    size_t base = (size_t)row * D_MODEL + tid * 4;
    *(float4*)(out + base) = ov;
    if (WB) {
        float r0, r1, r2, r3;
        uint2 hp, lp;
        hp.x = pack2(ov.x, ov.y, r0, r1);
        hp.y = pack2(ov.z, ov.w, r2, r3);
        lp.x = pack2lo(r0, r1);
        lp.y = pack2lo(r2, r3);
        *(uint2*)(oh + base) = hp;
        *(uint2*)(ol + base) = lp;
    }
}

// ---------------- head ----------------
__global__ void head_kernel(float* __restrict__ out, const float* __restrict__ W,
                            const float* __restrict__ hb) {
    __shared__ float c[D_MODEL];
    int b = blockIdx.y;
    int n = blockIdx.x * 128 + threadIdx.x;
#pragma unroll
    for (int rep = 0; rep < 2; rep++) {
        int idx = rep * 128 + threadIdx.x;
        *(float4*)&c[idx * 4] = *(const float4*)(g_cls + (size_t)b * D_MODEL + idx * 4);
    }
    __syncthreads();
    const float4* W4 = (const float4*)(W + (size_t)n * D_MODEL);
    const float4* c4 = (const float4*)c;
    float acc = 0.f;
#pragma unroll 8
    for (int k = 0; k < D_MODEL / 4; k++) {
        float4 w = W4[k], cc = c4[k];
        acc += w.x * cc.x + w.y * cc.y + w.z * cc.z + w.w * cc.w;
    }
    out[(size_t)b * D_MODEL + n] = acc + hb[n];
}

// ---------------- launcher ----------------
extern "C" void kernel_launch(void* const* d_in, const int* in_sizes, int n_in,
                              void* d_out, int out_size) {
    const int*   ids  = (const int*)  d_in[0];
    const float* tok  = (const float*)d_in[1];
    const float* pos  = (const float*)d_in[2];
    const float* Wqkv = (const float*)d_in[3];
    const float* bqkv = (const float*)d_in[4];
    const float* Wo   = (const float*)d_in[5];
    const float* bo   = (const float*)d_in[6];
    const float* ln1g = (const float*)d_in[7];
    const float* ln1b = (const float*)d_in[8];
    const float* W1   = (const float*)d_in[9];
    const float* b1   = (const float*)d_in[10];
    const float* W2   = (const float*)d_in[11];
    const float* b2   = (const float*)d_in[12];
    const float* ln2g = (const float*)d_in[13];
    const float* ln2b = (const float*)d_in[14];
    const float* hg   = (const float*)d_in[15];
    const float* hbln = (const float*)d_in[16];
    const float* hW   = (const float*)d_in[17];
    const float* hb   = (const float*)d_in[18];
    float* out = (float*)d_out;

    float *px, *ptmp, *pcls;
    __nv_bfloat16 *pwh, *pwl, *pxh, *pxl, *pah, *pal, *pfh, *pfl;
    cudaGetSymbolAddress((void**)&px,   g_x);
    cudaGetSymbolAddress((void**)&ptmp, g_tmp);
    cudaGetSymbolAddress((void**)&pcls, g_cls);
    cudaGetSymbolAddress((void**)&pwh,  g_wh);
    cudaGetSymbolAddress((void**)&pwl,  g_wl);
    cudaGetSymbolAddress((void**)&pxh,  g_xh);
    cudaGetSymbolAddress((void**)&pxl,  g_xl);
    cudaGetSymbolAddress((void**)&pah,  g_ah);
    cudaGetSymbolAddress((void**)&pal,  g_al);
    cudaGetSymbolAddress((void**)&pfh,  g_fh);
    cudaGetSymbolAddress((void**)&pfl,  g_fl);

    cudaFuncSetAttribute(gemm_mma<0>, cudaFuncAttributeMaxDynamicSharedMemorySize, GSMEM2);
    cudaFuncSetAttribute(gemm_mma<1>, cudaFuncAttributeMaxDynamicSharedMemorySize, GSMEM2);
    cudaFuncSetAttribute(gemm_mma<2>, cudaFuncAttributeMaxDynamicSharedMemorySize, GSMEM2);
    cudaFuncSetAttribute(attn_tc, cudaFuncAttributeMaxDynamicSharedMemorySize, AT_SMEM);

    mask_kernel <<<M_ROWS / 256, 256>>>(ids);
    embed_kernel<<<M_ROWS * D_MODEL / 1024, 256>>>(ids, tok, pos);

    // weight layout in g_wh/g_wl: [all Wqkv][all Wo][all W1][all W2]
    const size_t N_QKV = 3145728, N_WO = 1048576, N_W1 = 4194304, N_W2 = 4194304;
    const size_t O_QKV = 0;
    const size_t O_WO  = 6 * N_QKV;
    const size_t O_W1  = O_WO + 6 * N_WO;
    const size_t O_W2  = O_W1 + 6 * N_W1;
    cvt_kernel<<<(unsigned)(6*N_QKV/8/256), 256>>>(Wqkv, pwh + O_QKV, pwl + O_QKV, (int)(6*N_QKV/8));
    cvt_kernel<<<(unsigned)(6*N_WO /8/256), 256>>>(Wo,   pwh + O_WO,  pwl + O_WO,  (int)(6*N_WO/8));
    cvt_kernel<<<(unsigned)(6*N_W1 /8/256), 256>>>(W1,   pwh + O_W1,  pwl + O_W1,  (int)(6*N_W1/8));
    cvt_kernel<<<(unsigned)(6*N_W2 /8/256), 256>>>(W2,   pwh + O_W2,  pwl + O_W2,  (int)(6*N_W2/8));

    for (int i = 0; i < NLAYER; i++) {
        size_t o_qkv = O_QKV + (size_t)i * N_QKV;
        size_t o_wo  = O_WO  + (size_t)i * N_WO;
        size_t o_w1  = O_W1  + (size_t)i * N_W1;
        size_t o_w2  = O_W2  + (size_t)i * N_W2;

        gemm_mma<2><<<dim3(3 * D_MODEL / 128, M_ROWS / 256), 256, GSMEM2>>>(
            pxh, pxl, pwh + o_qkv, pwl + o_qkv, bqkv + (size_t)i * 3 * D_MODEL,
            nullptr, nullptr, nullptr, D_MODEL, 3 * D_MODEL);

        attn_tc<<<dim3(SEQ / 128, NHEAD, BATCH), 256, AT_SMEM>>>();

        gemm_mma<0><<<dim3(D_MODEL / 128, M_ROWS / 256), 256, GSMEM2>>>(
            pah, pal, pwh + o_wo, pwl + o_wo, bo + (size_t)i * D_MODEL,
            ptmp, nullptr, nullptr, D_MODEL, D_MODEL);

        ln_kernel<true, true><<<M_ROWS, 256>>>(px, pxh, pxl, px, ptmp,
            ln1g + (size_t)i * D_MODEL, ln1b + (size_t)i * D_MODEL, D_MODEL);

        gemm_mma<1><<<dim3(DIM_FF / 128, M_ROWS / 256), 256, GSMEM2>>>(
            pxh, pxl, pwh + o_w1, pwl + o_w1, b1 + (size_t)i * DIM_FF,
            nullptr, pfh, pfl, D_MODEL, DIM_FF);

        gemm_mma<0><<<dim3(D_MODEL / 128, M_ROWS / 256), 256, GSMEM2>>>(
            pfh, pfl, pwh + o_w2, pwl + o_w2, b2 + (size_t)i * D_MODEL,
            ptmp, nullptr, nullptr, DIM_FF, D_MODEL);

        ln_kernel<true, true><<<M_ROWS, 256>>>(px, pxh, pxl, px, ptmp,
            ln2g + (size_t)i * D_MODEL, ln2b + (size_t)i * D_MODEL, D_MODEL);
    }

    ln_kernel<false, false><<<BATCH, 256>>>(pcls, nullptr, nullptr, px, nullptr,
                                            hg, hbln, (size_t)SEQ * D_MODEL);
    head_kernel<<<dim3(D_MODEL / 128, BATCH), 128>>>(out, hW, hb);
}

// round 6
// speedup vs baseline: 3.1520x; 1.1118x over previous
#include <cuda_runtime.h>
#include <cuda_bf16.h>
#include <math.h>
#include <stdint.h>

#define D_MODEL 1024
#define NHEAD   16
#define DH      64
#define NLAYER  6
#define DIM_FF  4096
#define BATCH   8
#define SEQ     1024
#define M_ROWS  (BATCH*SEQ)   // 8192

// ---------------- scratch ----------------
__device__ float g_x   [M_ROWS * D_MODEL];
__device__ float g_tmp [M_ROWS * D_MODEL];
__device__ float g_cls [BATCH * D_MODEL];
__device__ unsigned char g_kpm[M_ROWS];

__device__ __nv_bfloat16 g_wh[75497472];
__device__ __nv_bfloat16 g_wl[75497472];
__device__ __nv_bfloat16 g_xh[M_ROWS * D_MODEL];
__device__ __nv_bfloat16 g_xl[M_ROWS * D_MODEL];
__device__ __nv_bfloat16 g_ah[M_ROWS * D_MODEL];
__device__ __nv_bfloat16 g_al[M_ROWS * D_MODEL];
__device__ __nv_bfloat16 g_fh[M_ROWS * DIM_FF];
__device__ __nv_bfloat16 g_fl[M_ROWS * DIM_FF];
__device__ __nv_bfloat16 g_qh[M_ROWS * D_MODEL];
__device__ __nv_bfloat16 g_ql[M_ROWS * D_MODEL];
__device__ __nv_bfloat16 g_kh[M_ROWS * D_MODEL];
__device__ __nv_bfloat16 g_kl[M_ROWS * D_MODEL];
__device__ __nv_bfloat16 g_vh[M_ROWS * D_MODEL];
__device__ __nv_bfloat16 g_vl[M_ROWS * D_MODEL];

// ---------------- helpers ----------------
__device__ __forceinline__ uint32_t smem_u32(const void* p) {
    uint32_t a;
    asm("{ .reg .u64 t; cvta.to.shared.u64 t, %1; cvt.u32.u64 %0, t; }"
        : "=r"(a) : "l"(p));
    return a;
}

#define CPA16(dst, src) \
    asm volatile("cp.async.cg.shared.global [%0], [%1], 16;" \
                 :: "r"(dst), "l"(src) : "memory")
#define CPA_COMMIT() asm volatile("cp.async.commit_group;" ::: "memory")
#define CPA_WAIT1()  asm volatile("cp.async.wait_group 1;" ::: "memory")
#define CPA_WAIT0()  asm volatile("cp.async.wait_group 0;" ::: "memory")

#define LDSM4(r, addr) \
    asm volatile("ldmatrix.sync.aligned.m8n8.x4.shared.b16 {%0,%1,%2,%3}, [%4];" \
                 : "=r"((r)[0]), "=r"((r)[1]), "=r"((r)[2]), "=r"((r)[3]) \
                 : "r"(addr))

__device__ __forceinline__ void mma16816(float* d, const uint32_t* a, const uint32_t* b) {
    asm volatile(
        "mma.sync.aligned.m16n8k16.row.col.f32.bf16.bf16.f32 "
        "{%0,%1,%2,%3}, {%4,%5,%6,%7}, {%8,%9}, {%0,%1,%2,%3};"
        : "+f"(d[0]), "+f"(d[1]), "+f"(d[2]), "+f"(d[3])
        : "r"(a[0]), "r"(a[1]), "r"(a[2]), "r"(a[3]), "r"(b[0]), "r"(b[1]));
}

__device__ __forceinline__ uint32_t pack2(float v0, float v1,
                                          float& r0, float& r1) {
    __nv_bfloat16 h0 = __float2bfloat16(v0);
    __nv_bfloat16 h1 = __float2bfloat16(v1);
    r0 = v0 - __bfloat162float(h0);
    r1 = v1 - __bfloat162float(h1);
    return ((uint32_t)__bfloat16_as_ushort(h1) << 16) | __bfloat16_as_ushort(h0);
}
__device__ __forceinline__ uint32_t pack2lo(float r0, float r1) {
    __nv_bfloat16 e0 = __float2bfloat16(r0);
    __nv_bfloat16 e1 = __float2bfloat16(r1);
    return ((uint32_t)__bfloat16_as_ushort(e1) << 16) | __bfloat16_as_ushort(e0);
}

// ---------------- mask ----------------
__global__ void mask_kernel(const int* __restrict__ ids) {
    int i = blockIdx.x * blockDim.x + threadIdx.x;
    if (i < M_ROWS)
        g_kpm[i] = (ids[i] == 0 && (i & (SEQ - 1)) != 0) ? 1 : 0;
}

// ---------------- embedding ----------------
__global__ void embed_kernel(const int* __restrict__ ids,
                             const float* __restrict__ tok,
                             const float* __restrict__ pos) {
    int idx4 = blockIdx.x * blockDim.x + threadIdx.x;
    int base = idx4 << 2;
    int bl   = base >> 10;
    int d    = base & 1023;
    int t    = ids[bl];
    float4 tv = *(const float4*)(tok + (size_t)t * D_MODEL + d);
    float4 pv = *(const float4*)(pos + (size_t)(bl & (SEQ - 1)) * D_MODEL + d);
    float4 o;
    o.x = tv.x + pv.x; o.y = tv.y + pv.y; o.z = tv.z + pv.z; o.w = tv.w + pv.w;
    *(float4*)(g_x + (size_t)base) = o;
    float r0, r1, r2, r3;
    uint2 hp, lp;
    hp.x = pack2(o.x, o.y, r0, r1);
    hp.y = pack2(o.z, o.w, r2, r3);
    lp.x = pack2lo(r0, r1);
    lp.y = pack2lo(r2, r3);
    *(uint2*)(g_xh + base) = hp;
    *(uint2*)(g_xl + base) = lp;
}

// ---------------- weight fp32 -> bf16 hi/lo ----------------
__global__ void cvt_kernel(const float* __restrict__ s,
                           __nv_bfloat16* __restrict__ h,
                           __nv_bfloat16* __restrict__ l, int n8) {
    int i = blockIdx.x * blockDim.x + threadIdx.x;
    if (i >= n8) return;
    float4 v0 = ((const float4*)s)[2 * i];
    float4 v1 = ((const float4*)s)[2 * i + 1];
    float r[8];
    uint4 hv, lv;
    hv.x = pack2(v0.x, v0.y, r[0], r[1]);
    hv.y = pack2(v0.z, v0.w, r[2], r[3]);
    hv.z = pack2(v1.x, v1.y, r[4], r[5]);
    hv.w = pack2(v1.z, v1.w, r[6], r[7]);
    lv.x = pack2lo(r[0], r[1]);
    lv.y = pack2lo(r[2], r[3]);
    lv.z = pack2lo(r[4], r[5]);
    lv.w = pack2lo(r[6], r[7]);
    ((uint4*)h)[i] = hv;
    ((uint4*)l)[i] = lv;
}

// ---------------- mma GEMM: C = A @ B^T + bias --------------------------------
// CTA tile 256x128, BK=32, 3-stage cp.async, one sync per chunk.
#define ROWB   80
#define ATILE  (256 * ROWB)
#define BTILE  (128 * ROWB)
#define STG    (2 * ATILE + 2 * BTILE)  // 61440
#define GSMEM2 (3 * STG)                // 184320

template <int MODE>
__global__ void __launch_bounds__(256, 1)
gemm_mma(const __nv_bfloat16* __restrict__ Ah, const __nv_bfloat16* __restrict__ Al,
         const __nv_bfloat16* __restrict__ Bh, const __nv_bfloat16* __restrict__ Bl,
         const float* __restrict__ bias,
         float* __restrict__ Cf,
         __nv_bfloat16* __restrict__ Ch, __nv_bfloat16* __restrict__ Cl,
         int K, int Ntot)
{
    extern __shared__ char sm8[];
    uint32_t sb = smem_u32(sm8);
    int tid = threadIdx.x, wid = tid >> 5, lane = tid & 31;
    int m0 = blockIdx.y << 8, n0 = blockIdx.x << 7;
    int wm = wid & 3, wn = wid >> 2;
    int g = lane >> 2, q = lane & 3;

    float acc[4][8][4];
#pragma unroll
    for (int mi = 0; mi < 4; ++mi)
#pragma unroll
        for (int ni = 0; ni < 8; ++ni)
#pragma unroll
            for (int r = 0; r < 4; ++r) acc[mi][ni][r] = 0.f;

    int NC = K >> 5;

    auto load_stage = [&](int s, int c) {
        uint32_t st = sb + (uint32_t)s * STG;
        long kb = (long)c << 5;
#pragma unroll
        for (int it = 0; it < 4; ++it) {
            int idx = it * 256 + tid;
            int r = idx >> 2, ch = idx & 3;
            uint32_t so = (uint32_t)r * ROWB + ch * 16;
            CPA16(st + so,         Ah + (size_t)(m0 + r) * K + kb + ch * 8);
            CPA16(st + ATILE + so, Al + (size_t)(m0 + r) * K + kb + ch * 8);
        }
#pragma unroll
        for (int it = 0; it < 2; ++it) {
            int idx = it * 256 + tid;
            int r = idx >> 2, ch = idx & 3;
            uint32_t so = (uint32_t)r * ROWB + ch * 16;
            CPA16(st + 2 * ATILE + so,         Bh + (size_t)(n0 + r) * K + kb + ch * 8);
            CPA16(st + 2 * ATILE + BTILE + so, Bl + (size_t)(n0 + r) * K + kb + ch * 8);
        }
    };

    uint32_t arow = (uint32_t)(wm * 64 + (lane & 15)) * ROWB + (lane >> 4) * 16;
    uint32_t brow = (uint32_t)(wn * 64 + ((lane >> 4) << 3) + (lane & 7)) * ROWB
                  + ((lane >> 3) & 1) * 16;

    load_stage(0, 0); CPA_COMMIT();
    load_stage(1, 1); CPA_COMMIT();

    int s = 0;
    for (int c = 0; c < NC; ++c) {
        if (c + 1 < NC) { CPA_WAIT1(); } else { CPA_WAIT0(); }
        __syncthreads();

        uint32_t base = sb + (uint32_t)s * STG;
        uint32_t aHb = base + arow, aLb = aHb + ATILE;
        uint32_t bHb = base + 2 * ATILE + brow, bLb = bHb + BTILE;

#pragma unroll
        for (int ks = 0; ks < 2; ++ks) {
            uint32_t ko = ks * 32;
            uint32_t ah[4][4], al[4][4];
#pragma unroll
            for (int mi = 0; mi < 4; ++mi) {
                LDSM4(ah[mi], aHb + mi * (16 * ROWB) + ko);
                LDSM4(al[mi], aLb + mi * (16 * ROWB) + ko);
            }
#pragma unroll
            for (int nj2 = 0; nj2 < 4; ++nj2) {
                uint32_t bh4[4], bl4[4];
                LDSM4(bh4, bHb + nj2 * (16 * ROWB) + ko);
                LDSM4(bl4, bLb + nj2 * (16 * ROWB) + ko);
#pragma unroll
                for (int half = 0; half < 2; ++half) {
                    int ni = nj2 * 2 + half;
                    uint32_t bhh[2] = {bh4[half * 2], bh4[half * 2 + 1]};
                    uint32_t bll[2] = {bl4[half * 2], bl4[half * 2 + 1]};
#pragma unroll
                    for (int mi = 0; mi < 4; ++mi) {
                        mma16816(acc[mi][ni], ah[mi], bhh);
                        mma16816(acc[mi][ni], ah[mi], bll);
                        mma16816(acc[mi][ni], al[mi], bhh);
                    }
                }
            }
        }

        if (c + 2 < NC) {
            int ws = s + 2; if (ws >= 3) ws -= 3;
            load_stage(ws, c + 2);
            CPA_COMMIT();
        }
        if (++s == 3) s = 0;
    }

    // ---- epilogue ----
#pragma unroll
    for (int mi = 0; mi < 4; ++mi) {
#pragma unroll
        for (int ni = 0; ni < 8; ++ni) {
            int col = n0 + wn * 64 + ni * 8 + q * 2;
            float2 bv = *(const float2*)(bias + col);
            float* a = acc[mi][ni];
#pragma unroll
            for (int half = 0; half < 2; ++half) {
                int row = m0 + wm * 64 + mi * 16 + g + half * 8;
                float v0 = a[half * 2 + 0] + bv.x;
                float v1 = a[half * 2 + 1] + bv.y;
                if (MODE == 0) {
                    float2 o; o.x = v0; o.y = v1;
                    *(float2*)(Cf + (size_t)row * Ntot + col) = o;
                } else if (MODE == 1) {
                    v0 = 0.5f * v0 * (1.0f + erff(v0 * 0.70710678118654752f));
                    v1 = 0.5f * v1 * (1.0f + erff(v1 * 0.70710678118654752f));
                    float r0, r1;
                    uint32_t hp = pack2(v0, v1, r0, r1);
                    uint32_t lp = pack2lo(r0, r1);
                    size_t off = (size_t)row * Ntot + col;
                    *(uint32_t*)(Ch + off) = hp;
                    *(uint32_t*)(Cl + off) = lp;
                } else {
                    int bb = row >> 10, l = row & 1023;
                    int cat = col >> 10, cc = col & 1023;
                    int hh = cc >> 6, d = cc & 63;
                    float r0, r1;
                    uint32_t hp = pack2(v0, v1, r0, r1);
                    uint32_t lp = pack2lo(r0, r1);
                    if (cat < 2) {
                        size_t base2 = (((size_t)bb * NHEAD + hh) * SEQ + l) * DH + d;
                        if (cat == 0) {
                            *(uint32_t*)(g_qh + base2) = hp;
                            *(uint32_t*)(g_ql + base2) = lp;
                        } else {
                            *(uint32_t*)(g_kh + base2) = hp;
                            *(uint32_t*)(g_kl + base2) = lp;
                        }
                    } else {
                        size_t base2 = (((size_t)bb * NHEAD + hh) * DH + d) * SEQ + l;
                        __nv_bfloat16 h0 = __ushort_as_bfloat16((unsigned short)(hp & 0xffff));
                        __nv_bfloat16 h1 = __ushort_as_bfloat16((unsigned short)(hp >> 16));
                        __nv_bfloat16 l0 = __ushort_as_bfloat16((unsigned short)(lp & 0xffff));
                        __nv_bfloat16 l1 = __ushort_as_bfloat16((unsigned short)(lp >> 16));
                        g_vh[base2] = h0; g_vh[base2 + SEQ] = h1;
                        g_vl[base2] = l0; g_vl[base2 + SEQ] = l1;
                    }
                }
            }
        }
    }
}

// ---------------- tensor-core flash attention (3-stage) ----------------------
#define AT_STR   144
#define AT_QB    (128 * AT_STR)
#define AT_KVST  (4 * 64 * AT_STR)               // 36864
#define AT_SMEM  (2 * AT_QB + 3 * AT_KVST + 3 * 64 * 4)
#define NKT      (SEQ / 64)

__global__ void __launch_bounds__(256, 1)
attn_tc() {
    extern __shared__ char sma[];
    uint32_t sb = smem_u32(sma);
    int tid = threadIdx.x, wid = tid >> 5, lane = tid & 31;
    int g = lane >> 2, q = lane & 3;
    int q0 = blockIdx.x << 7;
    int h  = blockIdx.y;
    int b  = blockIdx.z;
    size_t bh = (size_t)b * NHEAD + h;

    const __nv_bfloat16* qhp = g_qh + bh * SEQ * DH;
    const __nv_bfloat16* qlp = g_ql + bh * SEQ * DH;
    const __nv_bfloat16* khp = g_kh + bh * SEQ * DH;
    const __nv_bfloat16* klp = g_kl + bh * SEQ * DH;
    const __nv_bfloat16* vhp = g_vh + bh * DH * SEQ;
    const __nv_bfloat16* vlp = g_vl + bh * DH * SEQ;

    uint32_t sQh = sb, sQl = sb + AT_QB;
    uint32_t sKV0 = sb + 2 * AT_QB;
    float* msks = (float*)(sma + 2 * AT_QB + 3 * AT_KVST);

#pragma unroll
    for (int it = 0; it < 4; ++it) {
        int idx = it * 256 + tid;
        int r = idx >> 3, ch = idx & 7;
        uint32_t dst = (uint32_t)r * AT_STR + ch * 16;
        CPA16(sQh + dst, qhp + (size_t)(q0 + r) * DH + ch * 8);
        CPA16(sQl + dst, qlp + (size_t)(q0 + r) * DH + ch * 8);
    }

    auto load_kv = [&](int s, int t) {
        uint32_t st = sKV0 + (uint32_t)s * AT_KVST;
#pragma unroll
        for (int it = 0; it < 2; ++it) {
            int idx = it * 256 + tid;
            int r = idx >> 3, ch = idx & 7;
            uint32_t dst = (uint32_t)r * AT_STR + ch * 16;
            CPA16(st + dst,         khp + (size_t)(t * 64 + r) * DH + ch * 8);
            CPA16(st + 9216 + dst,  klp + (size_t)(t * 64 + r) * DH + ch * 8);
            CPA16(st + 18432 + dst, vhp + (size_t)r * SEQ + t * 64 + ch * 8);
            CPA16(st + 27648 + dst, vlp + (size_t)r * SEQ + t * 64 + ch * 8);
        }
        if (tid < 64)
            msks[s * 64 + tid] = g_kpm[b * SEQ + t * 64 + tid] ? 0.f : 1.f;
    };

    load_kv(0, 0); CPA_COMMIT();
    load_kv(1, 1); CPA_COMMIT();

    uint32_t qrow = (uint32_t)(wid * 16 + (lane & 15)) * AT_STR + (lane >> 4) * 16;
    uint32_t brow = (uint32_t)(((lane >> 4) << 3) + (lane & 7)) * AT_STR
                  + ((lane >> 3) & 1) * 16;

    uint32_t qfh[4][4], qfl[4][4];
    float cO[8][4];
#pragma unroll
    for (int j = 0; j < 8; ++j)
#pragma unroll
        for (int r = 0; r < 4; ++r) cO[j][r] = 0.f;
    float m0 = -1e30f, m1 = -1e30f, l0 = 0.f, l1 = 0.f;

    int s = 0;
    for (int t = 0; t < NKT; ++t) {
        if (t + 1 < NKT) { CPA_WAIT1(); } else { CPA_WAIT0(); }
        __syncthreads();

        if (t == 0) {
#pragma unroll
            for (int ks = 0; ks < 4; ++ks) {
                LDSM4(qfh[ks], sQh + qrow + ks * 32);
                LDSM4(qfl[ks], sQl + qrow + ks * 32);
            }
        }

        uint32_t kb = sKV0 + (uint32_t)s * AT_KVST;

        float cS[8][4];
#pragma unroll
        for (int j = 0; j < 8; ++j)
#pragma unroll
            for (int r = 0; r < 4; ++r) cS[j][r] = 0.f;

#pragma unroll
        for (int ks = 0; ks < 4; ++ks) {
            uint32_t ko = ks * 32;
#pragma unroll
            for (int nj2 = 0; nj2 < 4; ++nj2) {
                uint32_t kh4[4], kl4[4];
                LDSM4(kh4, kb + brow + nj2 * (16 * AT_STR) + ko);
                LDSM4(kl4, kb + 9216 + brow + nj2 * (16 * AT_STR) + ko);
#pragma unroll
                for (int half = 0; half < 2; ++half) {
                    int j = nj2 * 2 + half;
                    uint32_t bhh[2] = {kh4[half * 2], kh4[half * 2 + 1]};
                    uint32_t bll[2] = {kl4[half * 2], kl4[half * 2 + 1]};
                    mma16816(cS[j], qfh[ks], bhh);
                    mma16816(cS[j], qfh[ks], bll);
                    mma16816(cS[j], qfl[ks], bhh);
                }
            }
        }

        float lm0 = -1e30f, lm1 = -1e30f;
#pragma unroll
        for (int j = 0; j < 8; ++j) {
            cS[j][0] *= 0.125f; cS[j][1] *= 0.125f;
            cS[j][2] *= 0.125f; cS[j][3] *= 0.125f;
            lm0 = fmaxf(lm0, fmaxf(cS[j][0], cS[j][1]));
            lm1 = fmaxf(lm1, fmaxf(cS[j][2], cS[j][3]));
        }
        lm0 = fmaxf(lm0, __shfl_xor_sync(0xffffffffu, lm0, 1));
        lm0 = fmaxf(lm0, __shfl_xor_sync(0xffffffffu, lm0, 2));
        lm1 = fmaxf(lm1, __shfl_xor_sync(0xffffffffu, lm1, 1));
        lm1 = fmaxf(lm1, __shfl_xor_sync(0xffffffffu, lm1, 2));
        float mn0 = fmaxf(m0, lm0), mn1 = fmaxf(m1, lm1);
        float a0 = __expf(m0 - mn0), a1 = __expf(m1 - mn1);

        uint32_t PH[8][2], PL[8][2];
        float s0 = 0.f, s1 = 0.f;
#pragma unroll
        for (int j = 0; j < 8; ++j) {
            float mmA = msks[s * 64 + 8 * j + 2 * q];
            float mmB = msks[s * 64 + 8 * j + 2 * q + 1];
            float p0 = __expf(cS[j][0] - mn0) * mmA;
            float p1 = __expf(cS[j][1] - mn0) * mmB;
            float p2 = __expf(cS[j][2] - mn1) * mmA;
            float p3 = __expf(cS[j][3] - mn1) * mmB;
            s0 += p0 + p1; s1 += p2 + p3;
            float r0, r1, r2, r3;
            PH[j][0] = pack2(p0, p1, r0, r1);
            PH[j][1] = pack2(p2, p3, r2, r3);
            PL[j][0] = pack2lo(r0, r1);
            PL[j][1] = pack2lo(r2, r3);
        }
        s0 += __shfl_xor_sync(0xffffffffu, s0, 1);
        s0 += __shfl_xor_sync(0xffffffffu, s0, 2);
        s1 += __shfl_xor_sync(0xffffffffu, s1, 1);
        s1 += __shfl_xor_sync(0xffffffffu, s1, 2);
        l0 = l0 * a0 + s0; l1 = l1 * a1 + s1;
        m0 = mn0; m1 = mn1;

#pragma unroll
        for (int j = 0; j < 8; ++j) {
            cO[j][0] *= a0; cO[j][1] *= a0;
            cO[j][2] *= a1; cO[j][3] *= a1;
        }

#pragma unroll
        for (int kk = 0; kk < 4; ++kk) {
            uint32_t ah4[4] = {PH[2*kk][0], PH[2*kk][1], PH[2*kk+1][0], PH[2*kk+1][1]};
            uint32_t al4[4] = {PL[2*kk][0], PL[2*kk][1], PL[2*kk+1][0], PL[2*kk+1][1]};
            uint32_t ko = kk * 32;
#pragma unroll
            for (int nj2 = 0; nj2 < 4; ++nj2) {
                uint32_t vh4[4], vl4[4];
                LDSM4(vh4, kb + 18432 + brow + nj2 * (16 * AT_STR) + ko);
                LDSM4(vl4, kb + 27648 + brow + nj2 * (16 * AT_STR) + ko);
#pragma unroll
                for (int half = 0; half < 2; ++half) {
                    int j = nj2 * 2 + half;
                    uint32_t bhh[2] = {vh4[half * 2], vh4[half * 2 + 1]};
                    uint32_t bll[2] = {vl4[half * 2], vl4[half * 2 + 1]};
                    mma16816(cO[j], ah4, bhh);
                    mma16816(cO[j], ah4, bll);
                    mma16816(cO[j], al4, bhh);
                }
            }
        }

        if (t + 2 < NKT) {
            int ws = s + 2; if (ws >= 3) ws -= 3;
            load_kv(ws, t + 2);
            CPA_COMMIT();
        }
        if (++s == 3) s = 0;
    }

    float inv0 = 1.0f / l0, inv1 = 1.0f / l1;
    size_t row0 = (size_t)(b * SEQ + q0 + wid * 16 + g);
    size_t row1 = row0 + 8;
#pragma unroll
    for (int j = 0; j < 8; ++j) {
        int col = h * 64 + 8 * j + 2 * q;
        float r0, r1, r2, r3;
        uint32_t hp0 = pack2(cO[j][0] * inv0, cO[j][1] * inv0, r0, r1);
        uint32_t hp1 = pack2(cO[j][2] * inv1, cO[j][3] * inv1, r2, r3);
        uint32_t lp0 = pack2lo(r0, r1);
        uint32_t lp1 = pack2lo(r2, r3);
        *(uint32_t*)(g_ah + row0 * D_MODEL + col) = hp0;
        *(uint32_t*)(g_al + row0 * D_MODEL + col) = lp0;
        *(uint32_t*)(g_ah + row1 * D_MODEL + col) = hp1;
        *(uint32_t*)(g_al + row1 * D_MODEL + col) = lp1;
    }
}

// ---------------- LayerNorm (+residual) (+bf16 hi/lo out) -------------------
template <bool HASD, bool WB>
__global__ void ln_kernel(float* __restrict__ out,
                          __nv_bfloat16* __restrict__ oh, __nv_bfloat16* __restrict__ ol,
                          const float* __restrict__ x, const float* __restrict__ delta,
                          const float* __restrict__ g, const float* __restrict__ bta,
                          size_t in_row_stride) {
    __shared__ float vals[D_MODEL];
    __shared__ float red[256];
    __shared__ float red2[256];
    int row = blockIdx.x, tid = threadIdx.x;
    const float* xr = x + (size_t)row * in_row_stride;

    float4 v = *(const float4*)(xr + tid * 4);
    if (HASD) {
        float4 dv = *(const float4*)(delta + (size_t)row * D_MODEL + tid * 4);
        v.x += dv.x; v.y += dv.y; v.z += dv.z; v.w += dv.w;
    }
    *(float4*)&vals[tid * 4] = v;
    red[tid]  = v.x + v.y + v.z + v.w;
    red2[tid] = v.x * v.x + v.y * v.y + v.z * v.z + v.w * v.w;
    __syncthreads();
#pragma unroll
    for (int off = 128; off > 0; off >>= 1) {
        if (tid < off) { red[tid] += red[tid + off]; red2[tid] += red2[tid + off]; }
        __syncthreads();
    }
    float mean = red[0] * (1.0f / D_MODEL);
    float var  = red2[0] * (1.0f / D_MODEL) - mean * mean;
    float inv  = rsqrtf(var + 1e-5f);

    float4 vv = *(float4*)&vals[tid * 4];
    float4 g4 = *(const float4*)(g + tid * 4);
    float4 b4 = *(const float4*)(bta + tid * 4);
    float4 ov;
    ov.x = (vv.x - mean) * inv * g4.x + b4.x;
    ov.y = (vv.y - mean) * inv * g4.y + b4.y;
    ov.z = (vv.z - mean) * inv * g4.z + b4.z;
    ov.w = (vv.w - mean) * inv * g4.w + b4.w;
    size_t base = (size_t)row * D_MODEL + tid * 4;
    *(float4*)(out + base) = ov;
    if (WB) {
        float r0, r1, r2, r3;
        uint2 hp, lp;
        hp.x = pack2(ov.x, ov.y, r0, r1);
        hp.y = pack2(ov.z, ov.w, r2, r3);
        lp.x = pack2lo(r0, r1);
        lp.y = pack2lo(r2, r3);
        *(uint2*)(oh + base) = hp;
        *(uint2*)(ol + base) = lp;
    }
}

// ---------------- head ----------------
__global__ void head_kernel(float* __restrict__ out, const float* __restrict__ W,
                            const float* __restrict__ hb) {
    __shared__ float c[D_MODEL];
    int b = blockIdx.y;
    int n = blockIdx.x * 128 + threadIdx.x;
#pragma unroll
    for (int rep = 0; rep < 2; rep++) {
        int idx = rep * 128 + threadIdx.x;
        *(float4*)&c[idx * 4] = *(const float4*)(g_cls + (size_t)b * D_MODEL + idx * 4);
    }
    __syncthreads();
    const float4* W4 = (const float4*)(W + (size_t)n * D_MODEL);
    const float4* c4 = (const float4*)c;
    float acc = 0.f;
#pragma unroll 8
    for (int k = 0; k < D_MODEL / 4; k++) {
        float4 w = W4[k], cc = c4[k];
        acc += w.x * cc.x + w.y * cc.y + w.z * cc.z + w.w * cc.w;
    }
    out[(size_t)b * D_MODEL + n] = acc + hb[n];
}

// ---------------- launcher ----------------
extern "C" void kernel_launch(void* const* d_in, const int* in_sizes, int n_in,
                              void* d_out, int out_size) {
    const int*   ids  = (const int*)  d_in[0];
    const float* tok  = (const float*)d_in[1];
    const float* pos  = (const float*)d_in[2];
    const float* Wqkv = (const float*)d_in[3];
    const float* bqkv = (const float*)d_in[4];
    const float* Wo   = (const float*)d_in[5];
    const float* bo   = (const float*)d_in[6];
    const float* ln1g = (const float*)d_in[7];
    const float* ln1b = (const float*)d_in[8];
    const float* W1   = (const float*)d_in[9];
    const float* b1   = (const float*)d_in[10];
    const float* W2   = (const float*)d_in[11];
    const float* b2   = (const float*)d_in[12];
    const float* ln2g = (const float*)d_in[13];
    const float* ln2b = (const float*)d_in[14];
    const float* hg   = (const float*)d_in[15];
    const float* hbln = (const float*)d_in[16];
    const float* hW   = (const float*)d_in[17];
    const float* hb   = (const float*)d_in[18];
    float* out = (float*)d_out;

    float *px, *ptmp, *pcls;
    __nv_bfloat16 *pwh, *pwl, *pxh, *pxl, *pah, *pal, *pfh, *pfl;
    cudaGetSymbolAddress((void**)&px,   g_x);
    cudaGetSymbolAddress((void**)&ptmp, g_tmp);
    cudaGetSymbolAddress((void**)&pcls, g_cls);
    cudaGetSymbolAddress((void**)&pwh,  g_wh);
    cudaGetSymbolAddress((void**)&pwl,  g_wl);
    cudaGetSymbolAddress((void**)&pxh,  g_xh);
    cudaGetSymbolAddress((void**)&pxl,  g_xl);
    cudaGetSymbolAddress((void**)&pah,  g_ah);
    cudaGetSymbolAddress((void**)&pal,  g_al);
    cudaGetSymbolAddress((void**)&pfh,  g_fh);
    cudaGetSymbolAddress((void**)&pfl,  g_fl);

    cudaFuncSetAttribute(gemm_mma<0>, cudaFuncAttributeMaxDynamicSharedMemorySize, GSMEM2);
    cudaFuncSetAttribute(gemm_mma<1>, cudaFuncAttributeMaxDynamicSharedMemorySize, GSMEM2);
    cudaFuncSetAttribute(gemm_mma<2>, cudaFuncAttributeMaxDynamicSharedMemorySize, GSMEM2);
    cudaFuncSetAttribute(attn_tc, cudaFuncAttributeMaxDynamicSharedMemorySize, AT_SMEM);

    mask_kernel <<<M_ROWS / 256, 256>>>(ids);
    embed_kernel<<<M_ROWS * D_MODEL / 1024, 256>>>(ids, tok, pos);

    const size_t N_QKV = 3145728, N_WO = 1048576, N_W1 = 4194304, N_W2 = 4194304;
    const size_t O_QKV = 0;
    const size_t O_WO  = 6 * N_QKV;
    const size_t O_W1  = O_WO + 6 * N_WO;
    const size_t O_W2  = O_W1 + 6 * N_W1;
    cvt_kernel<<<(unsigned)(6*N_QKV/8/256), 256>>>(Wqkv, pwh + O_QKV, pwl + O_QKV, (int)(6*N_QKV/8));
    cvt_kernel<<<(unsigned)(6*N_WO /8/256), 256>>>(Wo,   pwh + O_WO,  pwl + O_WO,  (int)(6*N_WO/8));
    cvt_kernel<<<(unsigned)(6*N_W1 /8/256), 256>>>(W1,   pwh + O_W1,  pwl + O_W1,  (int)(6*N_W1/8));
    cvt_kernel<<<(unsigned)(6*N_W2 /8/256), 256>>>(W2,   pwh + O_W2,  pwl + O_W2,  (int)(6*N_W2/8));

    for (int i = 0; i < NLAYER; i++) {
        size_t o_qkv = O_QKV + (size_t)i * N_QKV;
        size_t o_wo  = O_WO  + (size_t)i * N_WO;
        size_t o_w1  = O_W1  + (size_t)i * N_W1;
        size_t o_w2  = O_W2  + (size_t)i * N_W2;

        gemm_mma<2><<<dim3(3 * D_MODEL / 128, M_ROWS / 256), 256, GSMEM2>>>(
            pxh, pxl, pwh + o_qkv, pwl + o_qkv, bqkv + (size_t)i * 3 * D_MODEL,
            nullptr, nullptr, nullptr, D_MODEL, 3 * D_MODEL);

        attn_tc<<<dim3(SEQ / 128, NHEAD, BATCH), 256, AT_SMEM>>>();

        gemm_mma<0><<<dim3(D_MODEL / 128, M_ROWS / 256), 256, GSMEM2>>>(
            pah, pal, pwh + o_wo, pwl + o_wo, bo + (size_t)i * D_MODEL,
            ptmp, nullptr, nullptr, D_MODEL, D_MODEL);

        ln_kernel<true, true><<<M_ROWS, 256>>>(px, pxh, pxl, px, ptmp,
            ln1g + (size_t)i * D_MODEL, ln1b + (size_t)i * D_MODEL, D_MODEL);

        gemm_mma<1><<<dim3(DIM_FF / 128, M_ROWS / 256), 256, GSMEM2>>>(
            pxh, pxl, pwh + o_w1, pwl + o_w1, b1 + (size_t)i * DIM_FF,
            nullptr, pfh, pfl, D_MODEL, DIM_FF);

        gemm_mma<0><<<dim3(D_MODEL / 128, M_ROWS / 256), 256, GSMEM2>>>(
            pfh, pfl, pwh + o_w2, pwl + o_w2, b2 + (size_t)i * D_MODEL,
            ptmp, nullptr, nullptr, DIM_FF, D_MODEL);

        ln_kernel<true, true><<<M_ROWS, 256>>>(px, pxh, pxl, px, ptmp,
            ln2g + (size_t)i * D_MODEL, ln2b + (size_t)i * D_MODEL, D_MODEL);
    }

    ln_kernel<false, false><<<BATCH, 256>>>(pcls, nullptr, nullptr, px, nullptr,
                                            hg, hbln, (size_t)SEQ * D_MODEL);
    head_kernel<<<dim3(D_MODEL / 128, BATCH), 128>>>(out, hW, hb);
}

// round 7
// speedup vs baseline: 3.2265x; 1.0236x over previous
#include <cuda_runtime.h>
#include <cuda_bf16.h>
#include <math.h>
#include <stdint.h>

#define D_MODEL 1024
#define NHEAD   16
#define DH      64
#define NLAYER  6
#define DIM_FF  4096
#define BATCH   8
#define SEQ     1024
#define M_ROWS  (BATCH*SEQ)   // 8192

// ---------------- scratch ----------------
__device__ float g_x   [M_ROWS * D_MODEL];
__device__ float g_tmp [M_ROWS * D_MODEL];
__device__ float g_cls [BATCH * D_MODEL];
__device__ unsigned char g_kpm[M_ROWS];

__device__ __nv_bfloat16 g_wh[75497472];
__device__ __nv_bfloat16 g_wl[75497472];
__device__ __nv_bfloat16 g_xh[M_ROWS * D_MODEL];
__device__ __nv_bfloat16 g_xl[M_ROWS * D_MODEL];
__device__ __nv_bfloat16 g_ah[M_ROWS * D_MODEL];
__device__ __nv_bfloat16 g_al[M_ROWS * D_MODEL];
__device__ __nv_bfloat16 g_fh[M_ROWS * DIM_FF];
__device__ __nv_bfloat16 g_fl[M_ROWS * DIM_FF];
__device__ __nv_bfloat16 g_qh[M_ROWS * D_MODEL];
__device__ __nv_bfloat16 g_ql[M_ROWS * D_MODEL];
__device__ __nv_bfloat16 g_kh[M_ROWS * D_MODEL];
__device__ __nv_bfloat16 g_kl[M_ROWS * D_MODEL];
__device__ __nv_bfloat16 g_vh[M_ROWS * D_MODEL];
__device__ __nv_bfloat16 g_vl[M_ROWS * D_MODEL];

// ---------------- helpers ----------------
__device__ __forceinline__ uint32_t smem_u32(const void* p) {
    uint32_t a;
    asm("{ .reg .u64 t; cvta.to.shared.u64 t, %1; cvt.u32.u64 %0, t; }"
        : "=r"(a) : "l"(p));
    return a;
}

#define CPA16(dst, src) \
    asm volatile("cp.async.cg.shared.global [%0], [%1], 16;" \
                 :: "r"(dst), "l"(src) : "memory")
#define CPA_COMMIT() asm volatile("cp.async.commit_group;" ::: "memory")
#define CPA_WAIT1()  asm volatile("cp.async.wait_group 1;" ::: "memory")
#define CPA_WAIT0()  asm volatile("cp.async.wait_group 0;" ::: "memory")

#define LDSM4(r, addr) \
    asm volatile("ldmatrix.sync.aligned.m8n8.x4.shared.b16 {%0,%1,%2,%3}, [%4];" \
                 : "=r"((r)[0]), "=r"((r)[1]), "=r"((r)[2]), "=r"((r)[3]) \
                 : "r"(addr))

__device__ __forceinline__ void mma16816(float* d, const uint32_t* a, const uint32_t* b) {
    asm volatile(
        "mma.sync.aligned.m16n8k16.row.col.f32.bf16.bf16.f32 "
        "{%0,%1,%2,%3}, {%4,%5,%6,%7}, {%8,%9}, {%0,%1,%2,%3};"
        : "+f"(d[0]), "+f"(d[1]), "+f"(d[2]), "+f"(d[3])
        : "r"(a[0]), "r"(a[1]), "r"(a[2]), "r"(a[3]), "r"(b[0]), "r"(b[1]));
}

// Truncation-based hi/lo split of a float pair.
// hi = exact top-16-bit truncation (packed via one PRMT),
// lo = rn-bf16 of the exact residual (one cvt.rn.bf16x2).
__device__ __forceinline__ void split2(float v0, float v1,
                                       uint32_t& hp, uint32_t& lp) {
    uint32_t u0 = __float_as_uint(v0), u1 = __float_as_uint(v1);
    asm("prmt.b32 %0, %1, %2, 0x7632;" : "=r"(hp) : "r"(u0), "r"(u1));
    float h0 = __uint_as_float(u0 & 0xffff0000u);
    float h1 = __uint_as_float(u1 & 0xffff0000u);
    float l0 = v0 - h0, l1 = v1 - h1;
    asm("cvt.rn.bf16x2.f32 %0, %1, %2;" : "=r"(lp) : "f"(l1), "f"(l0));
}

// ---------------- mask ----------------
__global__ void mask_kernel(const int* __restrict__ ids) {
    int i = blockIdx.x * blockDim.x + threadIdx.x;
    if (i < M_ROWS)
        g_kpm[i] = (ids[i] == 0 && (i & (SEQ - 1)) != 0) ? 1 : 0;
}

// ---------------- embedding ----------------
__global__ void embed_kernel(const int* __restrict__ ids,
                             const float* __restrict__ tok,
                             const float* __restrict__ pos) {
    int idx4 = blockIdx.x * blockDim.x + threadIdx.x;
    int base = idx4 << 2;
    int bl   = base >> 10;
    int d    = base & 1023;
    int t    = ids[bl];
    float4 tv = *(const float4*)(tok + (size_t)t * D_MODEL + d);
    float4 pv = *(const float4*)(pos + (size_t)(bl & (SEQ - 1)) * D_MODEL + d);
    float4 o;
    o.x = tv.x + pv.x; o.y = tv.y + pv.y; o.z = tv.z + pv.z; o.w = tv.w + pv.w;
    *(float4*)(g_x + (size_t)base) = o;
    uint2 hp, lp;
    split2(o.x, o.y, hp.x, lp.x);
    split2(o.z, o.w, hp.y, lp.y);
    *(uint2*)(g_xh + base) = hp;
    *(uint2*)(g_xl + base) = lp;
}

// ---------------- weight fp32 -> bf16 hi/lo ----------------
__global__ void cvt_kernel(const float* __restrict__ s,
                           __nv_bfloat16* __restrict__ h,
                           __nv_bfloat16* __restrict__ l, int n8) {
    int i = blockIdx.x * blockDim.x + threadIdx.x;
    if (i >= n8) return;
    float4 v0 = ((const float4*)s)[2 * i];
    float4 v1 = ((const float4*)s)[2 * i + 1];
    uint4 hv, lv;
    split2(v0.x, v0.y, hv.x, lv.x);
    split2(v0.z, v0.w, hv.y, lv.y);
    split2(v1.x, v1.y, hv.z, lv.z);
    split2(v1.z, v1.w, hv.w, lv.w);
    ((uint4*)h)[i] = hv;
    ((uint4*)l)[i] = lv;
}

// ---------------- mma GEMM: C = A @ B^T + bias --------------------------------
// CTA tile 256x128, BK=32, 3-stage cp.async, one sync per chunk.
#define ROWB   80
#define ATILE  (256 * ROWB)
#define BTILE  (128 * ROWB)
#define STG    (2 * ATILE + 2 * BTILE)  // 61440
#define GSMEM2 (3 * STG)                // 184320

template <int MODE>
__global__ void __launch_bounds__(256, 1)
gemm_mma(const __nv_bfloat16* __restrict__ Ah, const __nv_bfloat16* __restrict__ Al,
         const __nv_bfloat16* __restrict__ Bh, const __nv_bfloat16* __restrict__ Bl,
         const float* __restrict__ bias,
         float* __restrict__ Cf,
         __nv_bfloat16* __restrict__ Ch, __nv_bfloat16* __restrict__ Cl,
         int K, int Ntot)
{
    extern __shared__ char sm8[];
    uint32_t sb = smem_u32(sm8);
    int tid = threadIdx.x, wid = tid >> 5, lane = tid & 31;
    int m0 = blockIdx.y << 8, n0 = blockIdx.x << 7;
    int wm = wid & 3, wn = wid >> 2;
    int g = lane >> 2, q = lane & 3;

    float acc[4][8][4];
#pragma unroll
    for (int mi = 0; mi < 4; ++mi)
#pragma unroll
        for (int ni = 0; ni < 8; ++ni)
#pragma unroll
            for (int r = 0; r < 4; ++r) acc[mi][ni][r] = 0.f;

    int NC = K >> 5;

    auto load_stage = [&](int s, int c) {
        uint32_t st = sb + (uint32_t)s * STG;
        long kb = (long)c << 5;
#pragma unroll
        for (int it = 0; it < 4; ++it) {
            int idx = it * 256 + tid;
            int r = idx >> 2, ch = idx & 3;
            uint32_t so = (uint32_t)r * ROWB + ch * 16;
            CPA16(st + so,         Ah + (size_t)(m0 + r) * K + kb + ch * 8);
            CPA16(st + ATILE + so, Al + (size_t)(m0 + r) * K + kb + ch * 8);
        }
#pragma unroll
        for (int it = 0; it < 2; ++it) {
            int idx = it * 256 + tid;
            int r = idx >> 2, ch = idx & 3;
            uint32_t so = (uint32_t)r * ROWB + ch * 16;
            CPA16(st + 2 * ATILE + so,         Bh + (size_t)(n0 + r) * K + kb + ch * 8);
            CPA16(st + 2 * ATILE + BTILE + so, Bl + (size_t)(n0 + r) * K + kb + ch * 8);
        }
    };

    uint32_t arow = (uint32_t)(wm * 64 + (lane & 15)) * ROWB + (lane >> 4) * 16;
    uint32_t brow = (uint32_t)(wn * 64 + ((lane >> 4) << 3) + (lane & 7)) * ROWB
                  + ((lane >> 3) & 1) * 16;

    load_stage(0, 0); CPA_COMMIT();
    load_stage(1, 1); CPA_COMMIT();

    int s = 0;
    for (int c = 0; c < NC; ++c) {
        if (c + 1 < NC) { CPA_WAIT1(); } else { CPA_WAIT0(); }
        __syncthreads();

        uint32_t base = sb + (uint32_t)s * STG;
        uint32_t aHb = base + arow, aLb = aHb + ATILE;
        uint32_t bHb = base + 2 * ATILE + brow, bLb = bHb + BTILE;

#pragma unroll
        for (int ks = 0; ks < 2; ++ks) {
            uint32_t ko = ks * 32;
            uint32_t ah[4][4], al[4][4];
#pragma unroll
            for (int mi = 0; mi < 4; ++mi) {
                LDSM4(ah[mi], aHb + mi * (16 * ROWB) + ko);
                LDSM4(al[mi], aLb + mi * (16 * ROWB) + ko);
            }
#pragma unroll
            for (int nj2 = 0; nj2 < 4; ++nj2) {
                uint32_t bh4[4], bl4[4];
                LDSM4(bh4, bHb + nj2 * (16 * ROWB) + ko);
                LDSM4(bl4, bLb + nj2 * (16 * ROWB) + ko);
#pragma unroll
                for (int half = 0; half < 2; ++half) {
                    int ni = nj2 * 2 + half;
                    uint32_t bhh[2] = {bh4[half * 2], bh4[half * 2 + 1]};
                    uint32_t bll[2] = {bl4[half * 2], bl4[half * 2 + 1]};
#pragma unroll
                    for (int mi = 0; mi < 4; ++mi) {
                        mma16816(acc[mi][ni], ah[mi], bhh);
                        mma16816(acc[mi][ni], ah[mi], bll);
                        mma16816(acc[mi][ni], al[mi], bhh);
                    }
                }
            }
        }

        if (c + 2 < NC) {
            int ws = s + 2; if (ws >= 3) ws -= 3;
            load_stage(ws, c + 2);
            CPA_COMMIT();
        }
        if (++s == 3) s = 0;
    }

    // ---- epilogue ----
#pragma unroll
    for (int mi = 0; mi < 4; ++mi) {
#pragma unroll
        for (int ni = 0; ni < 8; ++ni) {
            int col = n0 + wn * 64 + ni * 8 + q * 2;
            float2 bv = *(const float2*)(bias + col);
            float* a = acc[mi][ni];
#pragma unroll
            for (int half = 0; half < 2; ++half) {
                int row = m0 + wm * 64 + mi * 16 + g + half * 8;
                float v0 = a[half * 2 + 0] + bv.x;
                float v1 = a[half * 2 + 1] + bv.y;
                if (MODE == 0) {
                    float2 o; o.x = v0; o.y = v1;
                    *(float2*)(Cf + (size_t)row * Ntot + col) = o;
                } else if (MODE == 1) {
                    v0 = 0.5f * v0 * (1.0f + erff(v0 * 0.70710678118654752f));
                    v1 = 0.5f * v1 * (1.0f + erff(v1 * 0.70710678118654752f));
                    uint32_t hp, lp;
                    split2(v0, v1, hp, lp);
                    size_t off = (size_t)row * Ntot + col;
                    *(uint32_t*)(Ch + off) = hp;
                    *(uint32_t*)(Cl + off) = lp;
                } else {
                    int bb = row >> 10, l = row & 1023;
                    int cat = col >> 10, cc = col & 1023;
                    int hh = cc >> 6, d = cc & 63;
                    if (cat == 0) { v0 *= 0.125f; v1 *= 0.125f; }  // fold softmax scale into Q
                    uint32_t hp, lp;
                    split2(v0, v1, hp, lp);
                    if (cat < 2) {
                        size_t base2 = (((size_t)bb * NHEAD + hh) * SEQ + l) * DH + d;
                        if (cat == 0) {
                            *(uint32_t*)(g_qh + base2) = hp;
                            *(uint32_t*)(g_ql + base2) = lp;
                        } else {
                            *(uint32_t*)(g_kh + base2) = hp;
                            *(uint32_t*)(g_kl + base2) = lp;
                        }
                    } else {
                        size_t base2 = (((size_t)bb * NHEAD + hh) * DH + d) * SEQ + l;
                        __nv_bfloat16 h0 = __ushort_as_bfloat16((unsigned short)(hp & 0xffff));
                        __nv_bfloat16 h1 = __ushort_as_bfloat16((unsigned short)(hp >> 16));
                        __nv_bfloat16 l0 = __ushort_as_bfloat16((unsigned short)(lp & 0xffff));
                        __nv_bfloat16 l1 = __ushort_as_bfloat16((unsigned short)(lp >> 16));
                        g_vh[base2] = h0; g_vh[base2 + SEQ] = h1;
                        g_vl[base2] = l0; g_vl[base2 + SEQ] = l1;
                    }
                }
            }
        }
    }
}

// ---------------- tensor-core flash attention (3-stage) ----------------------
#define AT_STR   144
#define AT_QB    (128 * AT_STR)
#define AT_KVST  (4 * 64 * AT_STR)               // 36864
#define AT_SMEM  (2 * AT_QB + 3 * AT_KVST + 3 * 64 * 4)
#define NKT      (SEQ / 64)

__global__ void __launch_bounds__(256, 1)
attn_tc() {
    extern __shared__ char sma[];
    uint32_t sb = smem_u32(sma);
    int tid = threadIdx.x, wid = tid >> 5, lane = tid & 31;
    int g = lane >> 2, q = lane & 3;
    int q0 = blockIdx.x << 7;
    int h  = blockIdx.y;
    int b  = blockIdx.z;
    size_t bh = (size_t)b * NHEAD + h;

    const __nv_bfloat16* qhp = g_qh + bh * SEQ * DH;
    const __nv_bfloat16* qlp = g_ql + bh * SEQ * DH;
    const __nv_bfloat16* khp = g_kh + bh * SEQ * DH;
    const __nv_bfloat16* klp = g_kl + bh * SEQ * DH;
    const __nv_bfloat16* vhp = g_vh + bh * DH * SEQ;
    const __nv_bfloat16* vlp = g_vl + bh * DH * SEQ;

    uint32_t sQh = sb, sQl = sb + AT_QB;
    uint32_t sKV0 = sb + 2 * AT_QB;
    float* msks = (float*)(sma + 2 * AT_QB + 3 * AT_KVST);

#pragma unroll
    for (int it = 0; it < 4; ++it) {
        int idx = it * 256 + tid;
        int r = idx >> 3, ch = idx & 7;
        uint32_t dst = (uint32_t)r * AT_STR + ch * 16;
        CPA16(sQh + dst, qhp + (size_t)(q0 + r) * DH + ch * 8);
        CPA16(sQl + dst, qlp + (size_t)(q0 + r) * DH + ch * 8);
    }

    auto load_kv = [&](int s, int t) {
        uint32_t st = sKV0 + (uint32_t)s * AT_KVST;
#pragma unroll
        for (int it = 0; it < 2; ++it) {
            int idx = it * 256 + tid;
            int r = idx >> 3, ch = idx & 7;
            uint32_t dst = (uint32_t)r * AT_STR + ch * 16;
            CPA16(st + dst,         khp + (size_t)(t * 64 + r) * DH + ch * 8);
            CPA16(st + 9216 + dst,  klp + (size_t)(t * 64 + r) * DH + ch * 8);
            CPA16(st + 18432 + dst, vhp + (size_t)r * SEQ + t * 64 + ch * 8);
            CPA16(st + 27648 + dst, vlp + (size_t)r * SEQ + t * 64 + ch * 8);
        }
        if (tid < 64)
            msks[s * 64 + tid] = g_kpm[b * SEQ + t * 64 + tid] ? 0.f : 1.f;
    };

    load_kv(0, 0); CPA_COMMIT();
    load_kv(1, 1); CPA_COMMIT();

    uint32_t qrow = (uint32_t)(wid * 16 + (lane & 15)) * AT_STR + (lane >> 4) * 16;
    uint32_t brow = (uint32_t)(((lane >> 4) << 3) + (lane & 7)) * AT_STR
                  + ((lane >> 3) & 1) * 16;

    uint32_t qfh[4][4], qfl[4][4];
    float cO[8][4];
#pragma unroll
    for (int j = 0; j < 8; ++j)
#pragma unroll
        for (int r = 0; r < 4; ++r) cO[j][r] = 0.f;
    float m0 = -1e30f, m1 = -1e30f, l0 = 0.f, l1 = 0.f;

    int s = 0;
    for (int t = 0; t < NKT; ++t) {
        if (t + 1 < NKT) { CPA_WAIT1(); } else { CPA_WAIT0(); }
        __syncthreads();

        if (t == 0) {
#pragma unroll
            for (int ks = 0; ks < 4; ++ks) {
                LDSM4(qfh[ks], sQh + qrow + ks * 32);
                LDSM4(qfl[ks], sQl + qrow + ks * 32);
            }
        }

        uint32_t kb = sKV0 + (uint32_t)s * AT_KVST;

        float cS[8][4];
#pragma unroll
        for (int j = 0; j < 8; ++j)
#pragma unroll
            for (int r = 0; r < 4; ++r) cS[j][r] = 0.f;

#pragma unroll
        for (int ks = 0; ks < 4; ++ks) {
            uint32_t ko = ks * 32;
#pragma unroll
            for (int nj2 = 0; nj2 < 4; ++nj2) {
                uint32_t kh4[4], kl4[4];
                LDSM4(kh4, kb + brow + nj2 * (16 * AT_STR) + ko);
                LDSM4(kl4, kb + 9216 + brow + nj2 * (16 * AT_STR) + ko);
#pragma unroll
                for (int half = 0; half < 2; ++half) {
                    int j = nj2 * 2 + half;
                    uint32_t bhh[2] = {kh4[half * 2], kh4[half * 2 + 1]};
                    uint32_t bll[2] = {kl4[half * 2], kl4[half * 2 + 1]};
                    mma16816(cS[j], qfh[ks], bhh);
                    mma16816(cS[j], qfh[ks], bll);
                    mma16816(cS[j], qfl[ks], bhh);
                }
            }
        }

        // Q pre-scaled by 1/8 — cS is already the scaled score
        float lm0 = -1e30f, lm1 = -1e30f;
#pragma unroll
        for (int j = 0; j < 8; ++j) {
            lm0 = fmaxf(lm0, fmaxf(cS[j][0], cS[j][1]));
            lm1 = fmaxf(lm1, fmaxf(cS[j][2], cS[j][3]));
        }
        lm0 = fmaxf(lm0, __shfl_xor_sync(0xffffffffu, lm0, 1));
        lm0 = fmaxf(lm0, __shfl_xor_sync(0xffffffffu, lm0, 2));
        lm1 = fmaxf(lm1, __shfl_xor_sync(0xffffffffu, lm1, 1));
        lm1 = fmaxf(lm1, __shfl_xor_sync(0xffffffffu, lm1, 2));
        float mn0 = fmaxf(m0, lm0), mn1 = fmaxf(m1, lm1);
        float a0 = __expf(m0 - mn0), a1 = __expf(m1 - mn1);

        uint32_t PH[8][2], PL[8][2];
        float s0 = 0.f, s1 = 0.f;
#pragma unroll
        for (int j = 0; j < 8; ++j) {
            float mmA = msks[s * 64 + 8 * j + 2 * q];
            float mmB = msks[s * 64 + 8 * j + 2 * q + 1];
            float p0 = __expf(cS[j][0] - mn0) * mmA;
            float p1 = __expf(cS[j][1] - mn0) * mmB;
            float p2 = __expf(cS[j][2] - mn1) * mmA;
            float p3 = __expf(cS[j][3] - mn1) * mmB;
            s0 += p0 + p1; s1 += p2 + p3;
            split2(p0, p1, PH[j][0], PL[j][0]);
            split2(p2, p3, PH[j][1], PL[j][1]);
        }
        s0 += __shfl_xor_sync(0xffffffffu, s0, 1);
        s0 += __shfl_xor_sync(0xffffffffu, s0, 2);
        s1 += __shfl_xor_sync(0xffffffffu, s1, 1);
        s1 += __shfl_xor_sync(0xffffffffu, s1, 2);
        l0 = l0 * a0 + s0; l1 = l1 * a1 + s1;
        m0 = mn0; m1 = mn1;

#pragma unroll
        for (int j = 0; j < 8; ++j) {
            cO[j][0] *= a0; cO[j][1] *= a0;
            cO[j][2] *= a1; cO[j][3] *= a1;
        }

#pragma unroll
        for (int kk = 0; kk < 4; ++kk) {
            uint32_t ah4[4] = {PH[2*kk][0], PH[2*kk][1], PH[2*kk+1][0], PH[2*kk+1][1]};
            uint32_t al4[4] = {PL[2*kk][0], PL[2*kk][1], PL[2*kk+1][0], PL[2*kk+1][1]};
            uint32_t ko = kk * 32;
#pragma unroll
            for (int nj2 = 0; nj2 < 4; ++nj2) {
                uint32_t vh4[4], vl4[4];
                LDSM4(vh4, kb + 18432 + brow + nj2 * (16 * AT_STR) + ko);
                LDSM4(vl4, kb + 27648 + brow + nj2 * (16 * AT_STR) + ko);
#pragma unroll
                for (int half = 0; half < 2; ++half) {
                    int j = nj2 * 2 + half;
                    uint32_t bhh[2] = {vh4[half * 2], vh4[half * 2 + 1]};
                    uint32_t bll[2] = {vl4[half * 2], vl4[half * 2 + 1]};
                    mma16816(cO[j], ah4, bhh);
                    mma16816(cO[j], ah4, bll);
                    mma16816(cO[j], al4, bhh);
                }
            }
        }

        if (t + 2 < NKT) {
            int ws = s + 2; if (ws >= 3) ws -= 3;
            load_kv(ws, t + 2);
            CPA_COMMIT();
        }
        if (++s == 3) s = 0;
    }

    float inv0 = 1.0f / l0, inv1 = 1.0f / l1;
    size_t row0 = (size_t)(b * SEQ + q0 + wid * 16 + g);
    size_t row1 = row0 + 8;
#pragma unroll
    for (int j = 0; j < 8; ++j) {
        int col = h * 64 + 8 * j + 2 * q;
        uint32_t hp0, lp0, hp1, lp1;
        split2(cO[j][0] * inv0, cO[j][1] * inv0, hp0, lp0);
        split2(cO[j][2] * inv1, cO[j][3] * inv1, hp1, lp1);
        *(uint32_t*)(g_ah + row0 * D_MODEL + col) = hp0;
        *(uint32_t*)(g_al + row0 * D_MODEL + col) = lp0;
        *(uint32_t*)(g_ah + row1 * D_MODEL + col) = hp1;
        *(uint32_t*)(g_al + row1 * D_MODEL + col) = lp1;
    }
}

// ---------------- LayerNorm (+residual) (+bf16 hi/lo out) -------------------
// warp-shuffle reduction, 2 barriers
template <bool HASD, bool WB>
__global__ void ln_kernel(float* __restrict__ out,
                          __nv_bfloat16* __restrict__ oh, __nv_bfloat16* __restrict__ ol,
                          const float* __restrict__ x, const float* __restrict__ delta,
                          const float* __restrict__ g, const float* __restrict__ bta,
                          size_t in_row_stride) {
    __shared__ float red1[8];
    __shared__ float red2[8];
    int row = blockIdx.x, tid = threadIdx.x;
    int lane = tid & 31, wid = tid >> 5;
    const float* xr = x + (size_t)row * in_row_stride;

    float4 v = *(const float4*)(xr + tid * 4);
    if (HASD) {
        float4 dv = *(const float4*)(delta + (size_t)row * D_MODEL + tid * 4);
        v.x += dv.x; v.y += dv.y; v.z += dv.z; v.w += dv.w;
    }
    float s  = v.x + v.y + v.z + v.w;
    float ss = v.x * v.x + v.y * v.y + v.z * v.z + v.w * v.w;
#pragma unroll
    for (int o = 16; o > 0; o >>= 1) {
        s  += __shfl_xor_sync(0xffffffffu, s, o);
        ss += __shfl_xor_sync(0xffffffffu, ss, o);
    }
    if (lane == 0) { red1[wid] = s; red2[wid] = ss; }
    __syncthreads();
    if (tid < 32) {
        float a = (lane < 8) ? red1[lane] : 0.f;
        float b = (lane < 8) ? red2[lane] : 0.f;
#pragma unroll
        for (int o = 4; o > 0; o >>= 1) {
            a += __shfl_xor_sync(0xffffffffu, a, o);
            b += __shfl_xor_sync(0xffffffffu, b, o);
        }
        if (lane == 0) { red1[0] = a; red2[0] = b; }
    }
    __syncthreads();
    float mean = red1[0] * (1.0f / D_MODEL);
    float var  = red2[0] * (1.0f / D_MODEL) - mean * mean;
    float inv  = rsqrtf(var + 1e-5f);

    float4 g4 = *(const float4*)(g + tid * 4);
    float4 b4 = *(const float4*)(bta + tid * 4);
    float4 ov;
    ov.x = (v.x - mean) * inv * g4.x + b4.x;
    ov.y = (v.y - mean) * inv * g4.y + b4.y;
    ov.z = (v.z - mean) * inv * g4.z + b4.z;
    ov.w = (v.w - mean) * inv * g4.w + b4.w;
    size_t base = (size_t)row * D_MODEL + tid * 4;
    *(float4*)(out + base) = ov;
    if (WB) {
        uint2 hp, lp;
        split2(ov.x, ov.y, hp.x, lp.x);
        split2(ov.z, ov.w, hp.y, lp.y);
        *(uint2*)(oh + base) = hp;
        *(uint2*)(ol + base) = lp;
    }
}

// ---------------- head ----------------
__global__ void head_kernel(float* __restrict__ out, const float* __restrict__ W,
                            const float* __restrict__ hb) {
    __shared__ float c[D_MODEL];
    int b = blockIdx.y;
    int n = blockIdx.x * 128 + threadIdx.x;
#pragma unroll
    for (int rep = 0; rep < 2; rep++) {
        int idx = rep * 128 + threadIdx.x;
        *(float4*)&c[idx * 4] = *(const float4*)(g_cls + (size_t)b * D_MODEL + idx * 4);
    }
    __syncthreads();
    const float4* W4 = (const float4*)(W + (size_t)n * D_MODEL);
    const float4* c4 = (const float4*)c;
    float acc = 0.f;
#pragma unroll 8
    for (int k = 0; k < D_MODEL / 4; k++) {
        float4 w = W4[k], cc = c4[k];
        acc += w.x * cc.x + w.y * cc.y + w.z * cc.z + w.w * cc.w;
    }
    out[(size_t)b * D_MODEL + n] = acc + hb[n];
}

// ---------------- launcher ----------------
extern "C" void kernel_launch(void* const* d_in, const int* in_sizes, int n_in,
                              void* d_out, int out_size) {
    const int*   ids  = (const int*)  d_in[0];
    const float* tok  = (const float*)d_in[1];
    const float* pos  = (const float*)d_in[2];
    const float* Wqkv = (const float*)d_in[3];
    const float* bqkv = (const float*)d_in[4];
    const float* Wo   = (const float*)d_in[5];
    const float* bo   = (const float*)d_in[6];
    const float* ln1g = (const float*)d_in[7];
    const float* ln1b = (const float*)d_in[8];
    const float* W1   = (const float*)d_in[9];
    const float* b1   = (const float*)d_in[10];
    const float* W2   = (const float*)d_in[11];
    const float* b2   = (const float*)d_in[12];
    const float* ln2g = (const float*)d_in[13];
    const float* ln2b = (const float*)d_in[14];
    const float* hg   = (const float*)d_in[15];
    const float* hbln = (const float*)d_in[16];
    const float* hW   = (const float*)d_in[17];
    const float* hb   = (const float*)d_in[18];
    float* out = (float*)d_out;

    float *px, *ptmp, *pcls;
    __nv_bfloat16 *pwh, *pwl, *pxh, *pxl, *pah, *pal, *pfh, *pfl;
    cudaGetSymbolAddress((void**)&px,   g_x);
    cudaGetSymbolAddress((void**)&ptmp, g_tmp);
    cudaGetSymbolAddress((void**)&pcls, g_cls);
    cudaGetSymbolAddress((void**)&pwh,  g_wh);
    cudaGetSymbolAddress((void**)&pwl,  g_wl);
    cudaGetSymbolAddress((void**)&pxh,  g_xh);
    cudaGetSymbolAddress((void**)&pxl,  g_xl);
    cudaGetSymbolAddress((void**)&pah,  g_ah);
    cudaGetSymbolAddress((void**)&pal,  g_al);
    cudaGetSymbolAddress((void**)&pfh,  g_fh);
    cudaGetSymbolAddress((void**)&pfl,  g_fl);

    cudaFuncSetAttribute(gemm_mma<0>, cudaFuncAttributeMaxDynamicSharedMemorySize, GSMEM2);
    cudaFuncSetAttribute(gemm_mma<1>, cudaFuncAttributeMaxDynamicSharedMemorySize, GSMEM2);
    cudaFuncSetAttribute(gemm_mma<2>, cudaFuncAttributeMaxDynamicSharedMemorySize, GSMEM2);
    cudaFuncSetAttribute(attn_tc, cudaFuncAttributeMaxDynamicSharedMemorySize, AT_SMEM);

    mask_kernel <<<M_ROWS / 256, 256>>>(ids);
    embed_kernel<<<M_ROWS * D_MODEL / 1024, 256>>>(ids, tok, pos);

    const size_t N_QKV = 3145728, N_WO = 1048576, N_W1 = 4194304, N_W2 = 4194304;
    const size_t O_QKV = 0;
    const size_t O_WO  = 6 * N_QKV;
    const size_t O_W1  = O_WO + 6 * N_WO;
    const size_t O_W2  = O_W1 + 6 * N_W1;
    cvt_kernel<<<(unsigned)(6*N_QKV/8/256), 256>>>(Wqkv, pwh + O_QKV, pwl + O_QKV, (int)(6*N_QKV/8));
    cvt_kernel<<<(unsigned)(6*N_WO /8/256), 256>>>(Wo,   pwh + O_WO,  pwl + O_WO,  (int)(6*N_WO/8));
    cvt_kernel<<<(unsigned)(6*N_W1 /8/256), 256>>>(W1,   pwh + O_W1,  pwl + O_W1,  (int)(6*N_W1/8));
    cvt_kernel<<<(unsigned)(6*N_W2 /8/256), 256>>>(W2,   pwh + O_W2,  pwl + O_W2,  (int)(6*N_W2/8));

    for (int i = 0; i < NLAYER; i++) {
        size_t o_qkv = O_QKV + (size_t)i * N_QKV;
        size_t o_wo  = O_WO  + (size_t)i * N_WO;
        size_t o_w1  = O_W1  + (size_t)i * N_W1;
        size_t o_w2  = O_W2  + (size_t)i * N_W2;

        gemm_mma<2><<<dim3(3 * D_MODEL / 128, M_ROWS / 256), 256, GSMEM2>>>(
            pxh, pxl, pwh + o_qkv, pwl + o_qkv, bqkv + (size_t)i * 3 * D_MODEL,
            nullptr, nullptr, nullptr, D_MODEL, 3 * D_MODEL);

        attn_tc<<<dim3(SEQ / 128, NHEAD, BATCH), 256, AT_SMEM>>>();

        gemm_mma<0><<<dim3(D_MODEL / 128, M_ROWS / 256), 256, GSMEM2>>>(
            pah, pal, pwh + o_wo, pwl + o_wo, bo + (size_t)i * D_MODEL,
            ptmp, nullptr, nullptr, D_MODEL, D_MODEL);

        ln_kernel<true, true><<<M_ROWS, 256>>>(px, pxh, pxl, px, ptmp,
            ln1g + (size_t)i * D_MODEL, ln1b + (size_t)i * D_MODEL, D_MODEL);

        gemm_mma<1><<<dim3(DIM_FF / 128, M_ROWS / 256), 256, GSMEM2>>>(
            pxh, pxl, pwh + o_w1, pwl + o_w1, b1 + (size_t)i * DIM_FF,
            nullptr, pfh, pfl, D_MODEL, DIM_FF);

        gemm_mma<0><<<dim3(D_MODEL / 128, M_ROWS / 256), 256, GSMEM2>>>(
            pfh, pfl, pwh + o_w2, pwl + o_w2, b2 + (size_t)i * D_MODEL,
            ptmp, nullptr, nullptr, DIM_FF, D_MODEL);

        ln_kernel<true, true><<<M_ROWS, 256>>>(px, pxh, pxl, px, ptmp,
            ln2g + (size_t)i * D_MODEL, ln2b + (size_t)i * D_MODEL, D_MODEL);
    }

    ln_kernel<false, false><<<BATCH, 256>>>(pcls, nullptr, nullptr, px, nullptr,
                                            hg, hbln, (size_t)SEQ * D_MODEL);
    head_kernel<<<dim3(D_MODEL / 128, BATCH), 128>>>(out, hW, hb);
}